// round 1
// baseline (speedup 1.0000x reference)
#include <cuda_runtime.h>
#include <math.h>

// Problem constants (fixed by the dataset)
#define NMAX 50000
#define EMAX 800000
#define ETOTMAX (EMAX + NMAX)

// ---------------- scratch (static device globals; no allocation) -------------
__device__ float g_h1[NMAX * 256];      // x @ W1
__device__ float g_out1[NMAX * 256];    // layer1 aggregation -> (in-place) LN+ELU
__device__ float g_h2[NMAX * 128];      // h @ W2
__device__ float g_out2[NMAX * 128];    // layer2 aggregation
__device__ float g_alpha1[(size_t)ETOTMAX * 8];
__device__ float g_alpha2[ETOTMAX];
__device__ float g_als1[NMAX * 8];
__device__ float g_ald1[NMAX * 8];
__device__ float g_ales[NMAX * 8];      // self-loop edge attention logits
__device__ float g_mx1[NMAX * 8];
__device__ float g_den1[NMAX * 8];
__device__ float g_als2[NMAX];
__device__ float g_ald2[NMAX];
__device__ float g_mx2[NMAX];
__device__ float g_den2[NMAX];
__device__ float g_cnt[NMAX];
__device__ float g_selfattr[NMAX * 64];
__device__ float g_ve[64 * 8];          // We1 collapsed against att_e1
__device__ float g_rae[6 * 8];          // per-relation edge-attention logits

// ---------------- helpers ----------------------------------------------------
__device__ __forceinline__ void atomicMaxF(float* addr, float val) {
    if (val >= 0.f)
        atomicMax((int*)addr, __float_as_int(val));
    else
        atomicMin((unsigned int*)addr, __float_as_uint(val));
}

// ---------------- init --------------------------------------------------------
__global__ void init_kernel(int Nn) {
    int total = Nn * 256;
    for (int idx = blockIdx.x * blockDim.x + threadIdx.x; idx < total;
         idx += gridDim.x * blockDim.x) {
        g_out1[idx] = 0.f;
        if (idx < Nn * 128) g_out2[idx] = 0.f;
        if (idx < Nn * 64) g_selfattr[idx] = 0.f;
        if (idx < Nn * 8) { g_mx1[idx] = -INFINITY; g_den1[idx] = 0.f; }
        if (idx < Nn) {
            g_mx2[idx] = -INFINITY; g_den2[idx] = 0.f; g_cnt[idx] = 0.f;
        }
    }
}

// ---------------- collapse edge-feature attention -----------------------------
// v_e[d][h] = sum_c We1[d, h*32+c] * att_e1[h, c]
// rae[r][h] = sum_d rel_emb[r, d] * v_e[d][h]
__global__ void prep_kernel(const float* __restrict__ We1,
                            const float* __restrict__ atte,
                            const float* __restrict__ rel_emb) {
    __shared__ float sve[64 * 8];
    int t = threadIdx.x;                 // 512 threads
    int d = t >> 3, h = t & 7;
    float s = 0.f;
    #pragma unroll
    for (int c = 0; c < 32; ++c)
        s += We1[d * 256 + h * 32 + c] * atte[h * 32 + c];
    sve[t] = s;
    g_ve[t] = s;
    __syncthreads();
    if (t < 48) {
        int r = t >> 3, hh = t & 7;
        float acc = 0.f;
        #pragma unroll
        for (int dd = 0; dd < 64; ++dd)
            acc += rel_emb[r * 64 + dd] * sve[dd * 8 + hh];
        g_rae[t] = acc;
    }
}

// ---------------- self-loop attr = mean of incoming rel features --------------
__global__ void sattr_kernel(const int* __restrict__ dst0,
                             const int* __restrict__ etype,
                             const float* __restrict__ rel_emb, int E) {
    int idx = blockIdx.x * blockDim.x + threadIdx.x;
    if (idx >= E * 64) return;
    int e = idx >> 6, d = idx & 63;
    int dn = dst0[e];
    atomicAdd(&g_selfattr[(size_t)dn * 64 + d], rel_emb[etype[e] * 64 + d]);
    if (d == 0) atomicAdd(&g_cnt[dn], 1.0f);
}

__global__ void ales_kernel(int Nn) {
    int idx = blockIdx.x * blockDim.x + threadIdx.x;
    if (idx >= Nn * 8) return;
    int n = idx >> 3, h = idx & 7;
    const float* sp = g_selfattr + (size_t)n * 64;
    float s = 0.f;
    #pragma unroll
    for (int d = 0; d < 64; ++d) s += sp[d] * g_ve[d * 8 + h];
    g_ales[idx] = s / fmaxf(g_cnt[n], 1.0f);
}

// ---------------- SGEMM: C[M,N] = A[M,K] @ B[K,N], row-major ------------------
template <int BM, int BN, int BK, int TM, int TN>
__global__ void sgemm_kernel(const float* __restrict__ A,
                             const float* __restrict__ B,
                             float* __restrict__ C, int M, int N, int K) {
    __shared__ float As[BK][BM];
    __shared__ float Bs[BK][BN];
    const int tid = threadIdx.x;                 // 256 threads
    const int bm0 = blockIdx.x * BM;
    const int bn0 = blockIdx.y * BN;
    const int tx = tid % (BN / TN);
    const int ty = tid / (BN / TN);
    const int a_row = tid / (BK / 4);            // 2 loaders per row
    const int a_col = (tid % (BK / 4)) * 4;
    const int b_row = tid / (BN / 4);            // 32 loaders per row
    const int b_col = (tid % (BN / 4)) * 4;
    float acc[TM][TN] = {};
    for (int k0 = 0; k0 < K; k0 += BK) {
        float4 av = make_float4(0.f, 0.f, 0.f, 0.f);
        int arow = bm0 + a_row;
        if (arow < M)
            av = *reinterpret_cast<const float4*>(A + (size_t)arow * K + k0 + a_col);
        As[a_col + 0][a_row] = av.x;
        As[a_col + 1][a_row] = av.y;
        As[a_col + 2][a_row] = av.z;
        As[a_col + 3][a_row] = av.w;
        *reinterpret_cast<float4*>(&Bs[b_row][b_col]) =
            *reinterpret_cast<const float4*>(B + (size_t)(k0 + b_row) * N + bn0 + b_col);
        __syncthreads();
        #pragma unroll
        for (int k = 0; k < BK; ++k) {
            float ra[TM], rb[TN];
            #pragma unroll
            for (int m = 0; m < TM; ++m) ra[m] = As[k][ty * TM + m];
            #pragma unroll
            for (int n = 0; n < TN; ++n) rb[n] = Bs[k][tx * TN + n];
            #pragma unroll
            for (int m = 0; m < TM; ++m)
                #pragma unroll
                for (int n = 0; n < TN; ++n) acc[m][n] += ra[m] * rb[n];
        }
        __syncthreads();
    }
    #pragma unroll
    for (int m = 0; m < TM; ++m) {
        int row = bm0 + ty * TM + m;
        if (row >= M) continue;
        #pragma unroll
        for (int n = 0; n < TN; n += 4) {
            float4 v = make_float4(acc[m][n], acc[m][n + 1], acc[m][n + 2], acc[m][n + 3]);
            *reinterpret_cast<float4*>(C + (size_t)row * N + bn0 + tx * TN + n) = v;
        }
    }
}

// ---------------- node attention logits (layer 1, 8 heads x 32ch) -------------
__global__ void attn1_kernel(const float* __restrict__ as_,
                             const float* __restrict__ ad_, int Nn) {
    int idx = blockIdx.x * blockDim.x + threadIdx.x;
    if (idx >= Nn * 8) return;
    int n = idx >> 3, h = idx & 7;
    const float* hp = g_h1 + (size_t)n * 256 + h * 32;
    const float* asp = as_ + h * 32;
    const float* adp = ad_ + h * 32;
    float s = 0.f, d = 0.f;
    #pragma unroll
    for (int c = 0; c < 32; ++c) {
        float v = hp[c];
        s += v * asp[c];
        d += v * adp[c];
    }
    g_als1[idx] = s;
    g_ald1[idx] = d;
}

// ---------------- layer-1 edge softmax ----------------------------------------
__global__ void edge_alpha1_kernel(const int* __restrict__ src0,
                                   const int* __restrict__ dst0,
                                   const int* __restrict__ etype, int E, int Etot) {
    int idx = blockIdx.x * blockDim.x + threadIdx.x;
    if (idx >= Etot * 8) return;
    int i = idx >> 3, h = idx & 7;
    int s, d; float ae;
    if (i < E) { s = src0[i]; d = dst0[i]; ae = g_rae[etype[i] * 8 + h]; }
    else       { s = i - E;  d = s;        ae = g_ales[s * 8 + h]; }
    float a = g_als1[s * 8 + h] + g_ald1[d * 8 + h] + ae;
    a = a > 0.f ? a : 0.2f * a;
    g_alpha1[idx] = a;
    atomicMaxF(&g_mx1[d * 8 + h], a);
}

__global__ void edge_exp1_kernel(const int* __restrict__ dst0, int E, int Etot) {
    int idx = blockIdx.x * blockDim.x + threadIdx.x;
    if (idx >= Etot * 8) return;
    int i = idx >> 3, h = idx & 7;
    int d = (i < E) ? dst0[i] : (i - E);
    float ex = expf(g_alpha1[idx] - g_mx1[d * 8 + h]);
    g_alpha1[idx] = ex;
    atomicAdd(&g_den1[d * 8 + h], ex);
}

__global__ void aggregate1_kernel(const int* __restrict__ src0,
                                  const int* __restrict__ dst0, int E, int Etot) {
    int idx = blockIdx.x * blockDim.x + threadIdx.x;
    if (idx >= Etot * 256) return;
    int i = idx >> 8;
    int hc = idx & 255;
    int h = hc >> 5;
    int s, d;
    if (i < E) { s = src0[i]; d = dst0[i]; } else { s = i - E; d = s; }
    float w = g_alpha1[(size_t)i * 8 + h] / (g_den1[d * 8 + h] + 1e-16f);
    atomicAdd(&g_out1[(size_t)d * 256 + hc], g_h1[(size_t)s * 256 + hc] * w);
}

// ---------------- LayerNorm(+bias) + ELU, in-place over g_out1 ----------------
__global__ void ln_elu1_kernel(const float* __restrict__ b,
                               const float* __restrict__ g,
                               const float* __restrict__ beta) {
    int n = blockIdx.x, t = threadIdx.x;  // 256 threads
    float v = g_out1[(size_t)n * 256 + t] + b[t];
    __shared__ float s1[256], s2[256];
    s1[t] = v; s2[t] = v * v;
    __syncthreads();
    for (int off = 128; off > 0; off >>= 1) {
        if (t < off) { s1[t] += s1[t + off]; s2[t] += s2[t + off]; }
        __syncthreads();
    }
    float m = s1[0] * (1.f / 256.f);
    float var = s2[0] * (1.f / 256.f) - m * m;
    float y = (v - m) * rsqrtf(var + 1e-5f) * g[t] + beta[t];
    g_out1[(size_t)n * 256 + t] = y > 0.f ? y : expm1f(y);
}

// ---------------- layer-2 attention logits ------------------------------------
__global__ void attn2_kernel(const float* __restrict__ as_,
                             const float* __restrict__ ad_) {
    int n = blockIdx.x, t = threadIdx.x;  // 128 threads
    float v = g_h2[(size_t)n * 128 + t];
    __shared__ float s1[128], s2[128];
    s1[t] = v * as_[t]; s2[t] = v * ad_[t];
    __syncthreads();
    for (int off = 64; off > 0; off >>= 1) {
        if (t < off) { s1[t] += s1[t + off]; s2[t] += s2[t + off]; }
        __syncthreads();
    }
    if (t == 0) { g_als2[n] = s1[0]; g_ald2[n] = s2[0]; }
}

__global__ void edge_alpha2_kernel(const int* __restrict__ src0,
                                   const int* __restrict__ dst0, int E, int Etot) {
    int i = blockIdx.x * blockDim.x + threadIdx.x;
    if (i >= Etot) return;
    int s, d;
    if (i < E) { s = src0[i]; d = dst0[i]; } else { s = i - E; d = s; }
    float a = g_als2[s] + g_ald2[d];
    a = a > 0.f ? a : 0.2f * a;
    g_alpha2[i] = a;
    atomicMaxF(&g_mx2[d], a);
}

__global__ void edge_exp2_kernel(const int* __restrict__ dst0, int E, int Etot) {
    int i = blockIdx.x * blockDim.x + threadIdx.x;
    if (i >= Etot) return;
    int d = (i < E) ? dst0[i] : (i - E);
    float ex = expf(g_alpha2[i] - g_mx2[d]);
    g_alpha2[i] = ex;
    atomicAdd(&g_den2[d], ex);
}

__global__ void aggregate2_kernel(const int* __restrict__ src0,
                                  const int* __restrict__ dst0, int E, int Etot) {
    int idx = blockIdx.x * blockDim.x + threadIdx.x;
    if (idx >= Etot * 128) return;
    int i = idx >> 7;
    int c = idx & 127;
    int s, d;
    if (i < E) { s = src0[i]; d = dst0[i]; } else { s = i - E; d = s; }
    float w = g_alpha2[i] / (g_den2[d] + 1e-16f);
    atomicAdd(&g_out2[(size_t)d * 128 + c], g_h2[(size_t)s * 128 + c] * w);
}

// ---------------- final LayerNorm -> output ------------------------------------
__global__ void ln2_kernel(const float* __restrict__ b,
                           const float* __restrict__ g,
                           const float* __restrict__ beta,
                           float* __restrict__ out) {
    int n = blockIdx.x, t = threadIdx.x;  // 128 threads
    float v = g_out2[(size_t)n * 128 + t] + b[t];
    __shared__ float s1[128], s2[128];
    s1[t] = v; s2[t] = v * v;
    __syncthreads();
    for (int off = 64; off > 0; off >>= 1) {
        if (t < off) { s1[t] += s1[t + off]; s2[t] += s2[t + off]; }
        __syncthreads();
    }
    float m = s1[0] * (1.f / 128.f);
    float var = s2[0] * (1.f / 128.f) - m * m;
    out[(size_t)n * 128 + t] = (v - m) * rsqrtf(var + 1e-5f) * g[t] + beta[t];
}

// ---------------- launch --------------------------------------------------------
extern "C" void kernel_launch(void* const* d_in, const int* in_sizes, int n_in,
                              void* d_out, int out_size) {
    const float* x       = (const float*)d_in[0];
    const int*   ei      = (const int*)d_in[1];
    const int*   etype   = (const int*)d_in[2];
    const float* rel_emb = (const float*)d_in[3];
    const float* W1      = (const float*)d_in[4];
    const float* as1     = (const float*)d_in[5];
    const float* ad1     = (const float*)d_in[6];
    const float* We1     = (const float*)d_in[7];
    const float* ae1     = (const float*)d_in[8];
    const float* b1      = (const float*)d_in[9];
    const float* g1      = (const float*)d_in[10];
    const float* beta1   = (const float*)d_in[11];
    const float* W2      = (const float*)d_in[12];
    const float* as2     = (const float*)d_in[13];
    const float* ad2     = (const float*)d_in[14];
    const float* b2      = (const float*)d_in[15];
    const float* g2      = (const float*)d_in[16];
    const float* beta2   = (const float*)d_in[17];
    float* out = (float*)d_out;

    const int E = in_sizes[2];
    const int Nn = in_sizes[0] / 768;
    const int Etot = E + Nn;
    const int* src0 = ei;
    const int* dst0 = ei + E;

    float *ph1, *pout1, *ph2;
    cudaGetSymbolAddress((void**)&ph1, g_h1);
    cudaGetSymbolAddress((void**)&pout1, g_out1);
    cudaGetSymbolAddress((void**)&ph2, g_h2);

    init_kernel<<<4096, 256>>>(Nn);
    prep_kernel<<<1, 512>>>(We1, ae1, rel_emb);
    sattr_kernel<<<(E * 64 + 255) / 256, 256>>>(dst0, etype, rel_emb, E);
    ales_kernel<<<(Nn * 8 + 255) / 256, 256>>>(Nn);

    // GEMM1: h1 = x @ W1   [Nn,768] x [768,256]
    {
        dim3 grid((Nn + 127) / 128, 256 / 128);
        sgemm_kernel<128, 128, 8, 8, 8><<<grid, 256>>>(x, W1, ph1, Nn, 256, 768);
    }
    attn1_kernel<<<(Nn * 8 + 255) / 256, 256>>>(as1, ad1, Nn);
    edge_alpha1_kernel<<<(Etot * 8 + 255) / 256, 256>>>(src0, dst0, etype, E, Etot);
    edge_exp1_kernel<<<(Etot * 8 + 255) / 256, 256>>>(dst0, E, Etot);
    {
        long long tot = (long long)Etot * 256;
        aggregate1_kernel<<<(unsigned)((tot + 255) / 256), 256>>>(src0, dst0, E, Etot);
    }
    ln_elu1_kernel<<<Nn, 256>>>(b1, g1, beta1);

    // GEMM2: h2 = h @ W2   [Nn,256] x [256,128]
    {
        dim3 grid((Nn + 127) / 128, 1);
        sgemm_kernel<128, 128, 8, 8, 8><<<grid, 256>>>(pout1, W2, ph2, Nn, 128, 256);
    }
    attn2_kernel<<<Nn, 128>>>(as2, ad2);
    edge_alpha2_kernel<<<(Etot + 255) / 256, 256>>>(src0, dst0, E, Etot);
    edge_exp2_kernel<<<(Etot + 255) / 256, 256>>>(dst0, E, Etot);
    {
        long long tot = (long long)Etot * 128;
        aggregate2_kernel<<<(unsigned)((tot + 255) / 256), 256>>>(src0, dst0, E, Etot);
    }
    ln2_kernel<<<Nn, 128>>>(b2, g2, beta2, out);
}

// round 2
// speedup vs baseline: 1.8661x; 1.8661x over previous
#include <cuda_runtime.h>
#include <math.h>

#define NMAX 50000
#define EMAX 800000

// ---------------- scratch (static device globals) ----------------------------
__device__ float g_h1[NMAX * 256];      // x @ W1
__device__ float g_out1[NMAX * 256];    // layer1 result (post LN+ELU)
__device__ float g_h2[NMAX * 128];      // h @ W2
__device__ float g_als1[NMAX * 8];
__device__ float g_ald1[NMAX * 8];
__device__ float g_als2[NMAX];
__device__ float g_ald2[NMAX];
__device__ float g_rae[6 * 8];          // per-relation collapsed edge-attn logits
__device__ int   g_off[NMAX + 1];
__device__ int   g_cur[NMAX];
__device__ int   g_csr_src[EMAX];
__device__ int   g_csr_type[EMAX];

// ---------------- init: zero degree counters ----------------------------------
__global__ void init_kernel(int Nn) {
    int i = blockIdx.x * blockDim.x + threadIdx.x;
    if (i < Nn) g_cur[i] = 0;
}

// ---------------- collapse edge-feature attention ------------------------------
// ve[d][h] = sum_c We1[d, h*32+c] * att_e1[h,c];  rae[r][h] = rel_emb[r,:] @ ve[:,h]
__global__ void prep_kernel(const float* __restrict__ We1,
                            const float* __restrict__ atte,
                            const float* __restrict__ rel_emb) {
    __shared__ float sve[64 * 8];
    int t = threadIdx.x;                 // 512 threads
    int d = t >> 3, h = t & 7;
    float s = 0.f;
    #pragma unroll
    for (int c = 0; c < 32; ++c)
        s += We1[d * 256 + h * 32 + c] * atte[h * 32 + c];
    sve[t] = s;
    __syncthreads();
    if (t < 48) {
        int r = t >> 3, hh = t & 7;
        float acc = 0.f;
        #pragma unroll
        for (int dd = 0; dd < 64; ++dd)
            acc += rel_emb[r * 64 + dd] * sve[dd * 8 + hh];
        g_rae[t] = acc;
    }
}

// ---------------- CSR build -----------------------------------------------------
__global__ void hist_kernel(const int* __restrict__ dst0, int E) {
    int e = blockIdx.x * blockDim.x + threadIdx.x;
    if (e < E) atomicAdd(&g_cur[dst0[e]], 1);
}

__global__ void scan_kernel(int Nn) {
    __shared__ int sh[1024];
    __shared__ int carry_s;
    int t = threadIdx.x;
    if (t == 0) carry_s = 0;
    __syncthreads();
    for (int base = 0; base < Nn; base += 1024) {
        int i = base + t;
        int v = (i < Nn) ? g_cur[i] : 0;
        sh[t] = v;
        __syncthreads();
        for (int o = 1; o < 1024; o <<= 1) {
            int add = (t >= o) ? sh[t - o] : 0;
            __syncthreads();
            sh[t] += add;
            __syncthreads();
        }
        int carry = carry_s;
        if (i < Nn) {
            int excl = carry + sh[t] - v;
            g_off[i] = excl;
            g_cur[i] = excl;
        }
        __syncthreads();
        if (t == 0) carry_s = carry + sh[1023];
        __syncthreads();
    }
    if (t == 0) g_off[Nn] = carry_s;
}

__global__ void scatter_kernel(const int* __restrict__ src0,
                               const int* __restrict__ dst0,
                               const int* __restrict__ etype, int E) {
    int e = blockIdx.x * blockDim.x + threadIdx.x;
    if (e >= E) return;
    int d = dst0[e];
    int pos = atomicAdd(&g_cur[d], 1);
    g_csr_src[pos]  = src0[e];
    g_csr_type[pos] = etype[e];
}

// ---------------- SGEMM: C[M,N] = A[M,K] @ B[K,N], row-major --------------------
template <int BM, int BN, int BK, int TM, int TN>
__global__ void sgemm_kernel(const float* __restrict__ A,
                             const float* __restrict__ B,
                             float* __restrict__ C, int M, int N, int K) {
    __shared__ float As[BK][BM];
    __shared__ float Bs[BK][BN];
    const int tid = threadIdx.x;                 // 256 threads
    const int bm0 = blockIdx.x * BM;
    const int bn0 = blockIdx.y * BN;
    const int tx = tid % (BN / TN);
    const int ty = tid / (BN / TN);
    const int a_row = tid / (BK / 4);
    const int a_col = (tid % (BK / 4)) * 4;
    const int b_row = tid / (BN / 4);
    const int b_col = (tid % (BN / 4)) * 4;
    float acc[TM][TN] = {};
    for (int k0 = 0; k0 < K; k0 += BK) {
        float4 av = make_float4(0.f, 0.f, 0.f, 0.f);
        int arow = bm0 + a_row;
        if (arow < M)
            av = *reinterpret_cast<const float4*>(A + (size_t)arow * K + k0 + a_col);
        As[a_col + 0][a_row] = av.x;
        As[a_col + 1][a_row] = av.y;
        As[a_col + 2][a_row] = av.z;
        As[a_col + 3][a_row] = av.w;
        *reinterpret_cast<float4*>(&Bs[b_row][b_col]) =
            *reinterpret_cast<const float4*>(B + (size_t)(k0 + b_row) * N + bn0 + b_col);
        __syncthreads();
        #pragma unroll
        for (int k = 0; k < BK; ++k) {
            float ra[TM], rb[TN];
            #pragma unroll
            for (int m = 0; m < TM; ++m) ra[m] = As[k][ty * TM + m];
            #pragma unroll
            for (int n = 0; n < TN; ++n) rb[n] = Bs[k][tx * TN + n];
            #pragma unroll
            for (int m = 0; m < TM; ++m)
                #pragma unroll
                for (int n = 0; n < TN; ++n) acc[m][n] += ra[m] * rb[n];
        }
        __syncthreads();
    }
    #pragma unroll
    for (int m = 0; m < TM; ++m) {
        int row = bm0 + ty * TM + m;
        if (row >= M) continue;
        #pragma unroll
        for (int n = 0; n < TN; n += 4) {
            float4 v = make_float4(acc[m][n], acc[m][n + 1], acc[m][n + 2], acc[m][n + 3]);
            *reinterpret_cast<float4*>(C + (size_t)row * N + bn0 + tx * TN + n) = v;
        }
    }
}

// ---------------- node attention logits (layer 1) -------------------------------
__global__ void attn1_kernel(const float* __restrict__ as_,
                             const float* __restrict__ ad_, int Nn) {
    int idx = blockIdx.x * blockDim.x + threadIdx.x;
    if (idx >= Nn * 8) return;
    int n = idx >> 3, h = idx & 7;
    const float* hp = g_h1 + (size_t)n * 256 + h * 32;
    const float* asp = as_ + h * 32;
    const float* adp = ad_ + h * 32;
    float s = 0.f, d = 0.f;
    #pragma unroll
    for (int c = 0; c < 32; ++c) {
        float v = hp[c];
        s += v * asp[c];
        d += v * adp[c];
    }
    g_als1[idx] = s;
    g_ald1[idx] = d;
}

// ---------------- layer-1: fused softmax + aggregation + bias + LN + ELU --------
// one block (256 thr = 8 warps) per dst node; warp h owns head h; thread t owns
// output channel t.
__global__ void gat1_node_kernel(const float* __restrict__ b,
                                 const float* __restrict__ g,
                                 const float* __restrict__ beta) {
    const int d = blockIdx.x;
    const int t = threadIdx.x;
    const int h = t >> 5, lane = t & 31;
    const int beg = g_off[d], end = g_off[d + 1];
    const int deg = end - beg;

    __shared__ int   sh_src[128];
    __shared__ float sh_ex[128 * 8];
    __shared__ float red1[256], red2[256];

    const float ald = g_ald1[d * 8 + h];

    // Pass A: per-head max of leaky(alpha) and sum of rae (for self-loop logit)
    float mx = -INFINITY, sumrae = 0.f;
    for (int e = beg + lane; e < end; e += 32) {
        int s = g_csr_src[e], r = g_csr_type[e];
        float rv = g_rae[r * 8 + h];
        float a = g_als1[s * 8 + h] + ald + rv;
        a = a > 0.f ? a : 0.2f * a;
        mx = fmaxf(mx, a);
        sumrae += rv;
    }
    #pragma unroll
    for (int o = 16; o; o >>= 1) {
        mx = fmaxf(mx, __shfl_xor_sync(0xffffffffu, mx, o));
        sumrae += __shfl_xor_sync(0xffffffffu, sumrae, o);
    }
    float aself = g_als1[d * 8 + h] + ald + sumrae / fmaxf((float)deg, 1.f);
    aself = aself > 0.f ? aself : 0.2f * aself;
    mx = fmaxf(mx, aself);

    float exs = __expf(aself - mx);
    float acc = exs * g_h1[(size_t)d * 256 + t];
    float den = (lane == 0) ? exs : 0.f;

    // Pass B: chunked exp + weighted gather-accumulate
    for (int c0 = beg; c0 < end; c0 += 128) {
        int csz = min(128, end - c0);
        for (int j = lane; j < csz; j += 32) {
            int e = c0 + j;
            int s = g_csr_src[e], r = g_csr_type[e];
            float a = g_als1[s * 8 + h] + ald + g_rae[r * 8 + h];
            a = a > 0.f ? a : 0.2f * a;
            float ex = __expf(a - mx);
            sh_ex[j * 8 + h] = ex;
            den += ex;
            if (h == 0) sh_src[j] = s;
        }
        __syncthreads();
        for (int j = 0; j < csz; ++j)
            acc += sh_ex[j * 8 + h] * g_h1[(size_t)sh_src[j] * 256 + t];
        __syncthreads();
    }
    #pragma unroll
    for (int o = 16; o; o >>= 1) den += __shfl_xor_sync(0xffffffffu, den, o);

    // bias + LayerNorm + ELU (block owns the full 256-wide row)
    float v = acc / (den + 1e-16f) + b[t];
    red1[t] = v; red2[t] = v * v;
    __syncthreads();
    #pragma unroll
    for (int o = 128; o > 0; o >>= 1) {
        if (t < o) { red1[t] += red1[t + o]; red2[t] += red2[t + o]; }
        __syncthreads();
    }
    float m = red1[0] * (1.f / 256.f);
    float var = red2[0] * (1.f / 256.f) - m * m;
    float y = (v - m) * rsqrtf(var + 1e-5f) * g[t] + beta[t];
    g_out1[(size_t)d * 256 + t] = y > 0.f ? y : expm1f(y);
}

// ---------------- layer-2 attention logits --------------------------------------
__global__ void attn2_kernel(const float* __restrict__ as_,
                             const float* __restrict__ ad_) {
    int n = blockIdx.x, t = threadIdx.x;  // 128 threads
    float v = g_h2[(size_t)n * 128 + t];
    __shared__ float s1[128], s2[128];
    s1[t] = v * as_[t]; s2[t] = v * ad_[t];
    __syncthreads();
    #pragma unroll
    for (int off = 64; off > 0; off >>= 1) {
        if (t < off) { s1[t] += s1[t + off]; s2[t] += s2[t + off]; }
        __syncthreads();
    }
    if (t == 0) { g_als2[n] = s1[0]; g_ald2[n] = s2[0]; }
}

// ---------------- layer-2: fused softmax + aggregation + bias + LN --------------
// one block (128 threads) per dst node; single head; thread t owns channel t.
__global__ void gat2_node_kernel(const float* __restrict__ b,
                                 const float* __restrict__ g,
                                 const float* __restrict__ beta,
                                 float* __restrict__ out) {
    const int d = blockIdx.x;
    const int t = threadIdx.x;
    const int beg = g_off[d], end = g_off[d + 1];

    __shared__ int   sh_src[128];
    __shared__ float sh_ex[128];
    __shared__ float red1[128], red2[128];

    const float ald = g_ald2[d];

    // Pass A: block max
    float mx = -INFINITY;
    for (int e = beg + t; e < end; e += 128) {
        float a = g_als2[g_csr_src[e]] + ald;
        a = a > 0.f ? a : 0.2f * a;
        mx = fmaxf(mx, a);
    }
    red1[t] = mx;
    __syncthreads();
    #pragma unroll
    for (int o = 64; o > 0; o >>= 1) {
        if (t < o) red1[t] = fmaxf(red1[t], red1[t + o]);
        __syncthreads();
    }
    mx = red1[0];
    float aself = g_als2[d] + ald;
    aself = aself > 0.f ? aself : 0.2f * aself;
    mx = fmaxf(mx, aself);
    __syncthreads();

    float exs = __expf(aself - mx);
    float acc = exs * g_h2[(size_t)d * 128 + t];
    float den_p = (t == 0) ? exs : 0.f;

    for (int c0 = beg; c0 < end; c0 += 128) {
        int csz = min(128, end - c0);
        if (t < csz) {
            int e = c0 + t;
            int s = g_csr_src[e];
            float a = g_als2[s] + ald;
            a = a > 0.f ? a : 0.2f * a;
            float ex = __expf(a - mx);
            sh_ex[t] = ex;
            sh_src[t] = s;
            den_p += ex;
        }
        __syncthreads();
        for (int j = 0; j < csz; ++j)
            acc += sh_ex[j] * g_h2[(size_t)sh_src[j] * 128 + t];
        __syncthreads();
    }
    red1[t] = den_p;
    __syncthreads();
    #pragma unroll
    for (int o = 64; o > 0; o >>= 1) {
        if (t < o) red1[t] += red1[t + o];
        __syncthreads();
    }
    float den = red1[0];
    __syncthreads();

    float v = acc / (den + 1e-16f) + b[t];
    red1[t] = v; red2[t] = v * v;
    __syncthreads();
    #pragma unroll
    for (int o = 64; o > 0; o >>= 1) {
        if (t < o) { red1[t] += red1[t + o]; red2[t] += red2[t + o]; }
        __syncthreads();
    }
    float m = red1[0] * (1.f / 128.f);
    float var = red2[0] * (1.f / 128.f) - m * m;
    out[(size_t)d * 128 + t] = (v - m) * rsqrtf(var + 1e-5f) * g[t] + beta[t];
}

// ---------------- launch ----------------------------------------------------------
extern "C" void kernel_launch(void* const* d_in, const int* in_sizes, int n_in,
                              void* d_out, int out_size) {
    const float* x       = (const float*)d_in[0];
    const int*   ei      = (const int*)d_in[1];
    const int*   etype   = (const int*)d_in[2];
    const float* rel_emb = (const float*)d_in[3];
    const float* W1      = (const float*)d_in[4];
    const float* as1     = (const float*)d_in[5];
    const float* ad1     = (const float*)d_in[6];
    const float* We1     = (const float*)d_in[7];
    const float* ae1     = (const float*)d_in[8];
    const float* b1      = (const float*)d_in[9];
    const float* g1      = (const float*)d_in[10];
    const float* beta1   = (const float*)d_in[11];
    const float* W2      = (const float*)d_in[12];
    const float* as2     = (const float*)d_in[13];
    const float* ad2     = (const float*)d_in[14];
    const float* b2      = (const float*)d_in[15];
    const float* g2      = (const float*)d_in[16];
    const float* beta2   = (const float*)d_in[17];
    float* out = (float*)d_out;

    const int E = in_sizes[2];
    const int Nn = in_sizes[0] / 768;
    const int* src0 = ei;
    const int* dst0 = ei + E;

    float *ph1, *pout1, *ph2;
    cudaGetSymbolAddress((void**)&ph1, g_h1);
    cudaGetSymbolAddress((void**)&pout1, g_out1);
    cudaGetSymbolAddress((void**)&ph2, g_h2);

    // CSR build + collapsed edge attention
    init_kernel<<<(Nn + 255) / 256, 256>>>(Nn);
    prep_kernel<<<1, 512>>>(We1, ae1, rel_emb);
    hist_kernel<<<(E + 255) / 256, 256>>>(dst0, E);
    scan_kernel<<<1, 1024>>>(Nn);
    scatter_kernel<<<(E + 255) / 256, 256>>>(src0, dst0, etype, E);

    // GEMM1: h1 = x @ W1   [Nn,768] x [768,256]
    {
        dim3 grid((Nn + 127) / 128, 2);
        sgemm_kernel<128, 128, 8, 8, 8><<<grid, 256>>>(x, W1, ph1, Nn, 256, 768);
    }
    attn1_kernel<<<(Nn * 8 + 255) / 256, 256>>>(as1, ad1, Nn);
    gat1_node_kernel<<<Nn, 256>>>(b1, g1, beta1);

    // GEMM2: h2 = out1 @ W2   [Nn,256] x [256,128]
    {
        dim3 grid((Nn + 127) / 128, 1);
        sgemm_kernel<128, 128, 8, 8, 8><<<grid, 256>>>(pout1, W2, ph2, Nn, 128, 256);
    }
    attn2_kernel<<<Nn, 128>>>(as2, ad2);
    gat2_node_kernel<<<Nn, 128>>>(b2, g2, beta2, out);
}

// round 3
// speedup vs baseline: 2.6942x; 1.4437x over previous
#include <cuda_runtime.h>
#include <math.h>
#include <stdint.h>

#define NMAX 50000
#define EMAX 800000

// ---------------- scratch (static device globals) ----------------------------
__device__ float g_h1[NMAX * 256];      // x @ W1
__device__ float g_out1[NMAX * 256];    // layer1 result (post LN+ELU)
__device__ float g_h2[NMAX * 128];      // h @ W2
__device__ float g_als1[NMAX * 8];
__device__ float g_ald1[NMAX * 8];
__device__ float g_als2[NMAX];
__device__ float g_ald2[NMAX];
__device__ float g_rae[6 * 8];
__device__ int   g_off[NMAX + 1];
__device__ int   g_cur[NMAX];
__device__ int   g_bsum[64];
__device__ int   g_csr_src[EMAX];
__device__ int   g_csr_type[EMAX];

// ---------------- init ----------------------------------------------------------
__global__ void init_kernel(int Nn) {
    int i = blockIdx.x * blockDim.x + threadIdx.x;
    if (i < Nn) g_cur[i] = 0;
}

// ---------------- collapse edge-feature attention -------------------------------
__global__ void prep_kernel(const float* __restrict__ We1,
                            const float* __restrict__ atte,
                            const float* __restrict__ rel_emb) {
    __shared__ float sve[64 * 8];
    int t = threadIdx.x;                 // 512 threads
    int d = t >> 3, h = t & 7;
    float s = 0.f;
    #pragma unroll
    for (int c = 0; c < 32; ++c)
        s += We1[d * 256 + h * 32 + c] * atte[h * 32 + c];
    sve[t] = s;
    __syncthreads();
    if (t < 48) {
        int r = t >> 3, hh = t & 7;
        float acc = 0.f;
        #pragma unroll
        for (int dd = 0; dd < 64; ++dd)
            acc += rel_emb[r * 64 + dd] * sve[dd * 8 + hh];
        g_rae[t] = acc;
    }
}

// ---------------- CSR build: hist -> 3-kernel parallel scan -> scatter ----------
__global__ void hist_kernel(const int* __restrict__ dst0, int E) {
    int e = blockIdx.x * blockDim.x + threadIdx.x;
    if (e < E) atomicAdd(&g_cur[dst0[e]], 1);
}

__global__ void scan_part_kernel(int Nn) {   // grid = ceil(Nn/1024), block = 1024
    __shared__ int sh[1024];
    int t = threadIdx.x;
    int i = blockIdx.x * 1024 + t;
    int v = (i < Nn) ? g_cur[i] : 0;
    sh[t] = v;
    __syncthreads();
    #pragma unroll
    for (int o = 1; o < 1024; o <<= 1) {
        int add = (t >= o) ? sh[t - o] : 0;
        __syncthreads();
        sh[t] += add;
        __syncthreads();
    }
    if (i < Nn) g_off[i] = sh[t] - v;        // block-local exclusive
    if (t == 1023) g_bsum[blockIdx.x] = sh[1023];
}

__global__ void scan_tops_kernel(int nb) {   // 1 block, 64 threads
    __shared__ int sh[64];
    int t = threadIdx.x;
    int v = (t < nb) ? g_bsum[t] : 0;
    sh[t] = v;
    __syncthreads();
    #pragma unroll
    for (int o = 1; o < 64; o <<= 1) {
        int add = (t >= o) ? sh[t - o] : 0;
        __syncthreads();
        sh[t] += add;
        __syncthreads();
    }
    g_bsum[t] = sh[t] - v;                   // exclusive
}

__global__ void scan_add_kernel(int Nn, int E) {
    int i = blockIdx.x * blockDim.x + threadIdx.x;
    if (i < Nn) {
        int o = g_off[i] + g_bsum[i >> 10];
        g_off[i] = o;
        g_cur[i] = o;
    }
    if (i == 0) g_off[Nn] = E;
}

__global__ void scatter_kernel(const int* __restrict__ src0,
                               const int* __restrict__ dst0,
                               const int* __restrict__ etype, int E) {
    int e = blockIdx.x * blockDim.x + threadIdx.x;
    if (e >= E) return;
    int d = dst0[e];
    int pos = atomicAdd(&g_cur[d], 1);
    g_csr_src[pos]  = src0[e];
    g_csr_type[pos] = etype[e];
}

// ---------------- TF32 tensor-core GEMM ------------------------------------------
// C[M,N] = A[M,K] @ B[K,N], row-major. BM=BN=128, BK=32, 256 thr (8 warps 2x4),
// warp tile 64x32 via mma.sync.m16n8k8.
__device__ __forceinline__ uint32_t f2tf32(float x) {
    uint32_t r;
    asm("cvt.rna.tf32.f32 %0, %1;" : "=r"(r) : "f"(x));
    return r;
}

__device__ __forceinline__ void mma_tf32(float* c, const uint32_t* a, const uint32_t* b) {
    asm volatile(
        "mma.sync.aligned.m16n8k8.row.col.f32.tf32.tf32.f32 "
        "{%0,%1,%2,%3}, {%4,%5,%6,%7}, {%8,%9}, {%0,%1,%2,%3};"
        : "+f"(c[0]), "+f"(c[1]), "+f"(c[2]), "+f"(c[3])
        : "r"(a[0]), "r"(a[1]), "r"(a[2]), "r"(a[3]), "r"(b[0]), "r"(b[1]));
}

#define AS_LD 33   // As stride (floats)
#define BS_LD 132  // Bs stride (floats)

__global__ void __launch_bounds__(256, 2)
gemm_tf32_kernel(const float* __restrict__ A, const float* __restrict__ B,
                 float* __restrict__ C, int M, int N, int K) {
    __shared__ uint32_t As[128 * AS_LD];
    __shared__ uint32_t Bs[32 * BS_LD];

    const int tid = threadIdx.x;
    const int lane = tid & 31, wid = tid >> 5;
    const int wm = (wid >> 2) * 64;          // 0 or 64
    const int wn = (wid & 3) * 32;           // 0..96
    const int bm0 = blockIdx.x * 128;
    const int bn0 = blockIdx.y * 128;

    const int a_r = tid >> 3;                // 0..31
    const int a_c = (tid & 7) * 4;           // 0..28
    const int b_r = tid >> 6;                // 0..3
    const int b_c = (tid & 63) * 2;          // 0..126, float2 per thread

    float acc[4][4][4];
    #pragma unroll
    for (int i = 0; i < 4; ++i)
        #pragma unroll
        for (int j = 0; j < 4; ++j)
            #pragma unroll
            for (int k = 0; k < 4; ++k) acc[i][j][k] = 0.f;

    for (int k0 = 0; k0 < K; k0 += 32) {
        // load A tile: 128 x 32
        #pragma unroll
        for (int r = 0; r < 4; ++r) {
            int row = a_r + r * 32;
            int grow = bm0 + row;
            float4 v = make_float4(0.f, 0.f, 0.f, 0.f);
            if (grow < M)
                v = *reinterpret_cast<const float4*>(A + (size_t)grow * K + k0 + a_c);
            uint32_t* p = As + row * AS_LD + a_c;
            p[0] = f2tf32(v.x); p[1] = f2tf32(v.y);
            p[2] = f2tf32(v.z); p[3] = f2tf32(v.w);
        }
        // load B tile: 32 x 128
        #pragma unroll
        for (int r = 0; r < 8; ++r) {
            int row = b_r + r * 4;
            float2 v = *reinterpret_cast<const float2*>(B + (size_t)(k0 + row) * N + bn0 + b_c);
            uint32_t* p = Bs + row * BS_LD + b_c;
            p[0] = f2tf32(v.x); p[1] = f2tf32(v.y);
        }
        __syncthreads();

        #pragma unroll
        for (int kk = 0; kk < 4; ++kk) {
            const int kb = kk * 8;
            uint32_t afrag[4][4], bfrag[4][2];
            #pragma unroll
            for (int mt = 0; mt < 4; ++mt) {
                int r0 = wm + mt * 16 + (lane >> 2);
                int c0 = kb + (lane & 3);
                afrag[mt][0] = As[r0 * AS_LD + c0];
                afrag[mt][1] = As[(r0 + 8) * AS_LD + c0];
                afrag[mt][2] = As[r0 * AS_LD + c0 + 4];
                afrag[mt][3] = As[(r0 + 8) * AS_LD + c0 + 4];
            }
            #pragma unroll
            for (int nt = 0; nt < 4; ++nt) {
                int n0 = wn + nt * 8 + (lane >> 2);
                int kr = kb + (lane & 3);
                bfrag[nt][0] = Bs[kr * BS_LD + n0];
                bfrag[nt][1] = Bs[(kr + 4) * BS_LD + n0];
            }
            #pragma unroll
            for (int mt = 0; mt < 4; ++mt)
                #pragma unroll
                for (int nt = 0; nt < 4; ++nt)
                    mma_tf32(acc[mt][nt], afrag[mt], bfrag[nt]);
        }
        __syncthreads();
    }

    // epilogue
    #pragma unroll
    for (int mt = 0; mt < 4; ++mt) {
        int row0 = bm0 + wm + mt * 16 + (lane >> 2);
        #pragma unroll
        for (int nt = 0; nt < 4; ++nt) {
            int col0 = bn0 + wn + nt * 8 + (lane & 3) * 2;
            if (row0 < M)
                *reinterpret_cast<float2*>(C + (size_t)row0 * N + col0) =
                    make_float2(acc[mt][nt][0], acc[mt][nt][1]);
            if (row0 + 8 < M)
                *reinterpret_cast<float2*>(C + (size_t)(row0 + 8) * N + col0) =
                    make_float2(acc[mt][nt][2], acc[mt][nt][3]);
        }
    }
}

// ---------------- node attention logits (layer 1) --------------------------------
__global__ void attn1_kernel(const float* __restrict__ as_,
                             const float* __restrict__ ad_, int Nn) {
    int idx = blockIdx.x * blockDim.x + threadIdx.x;
    if (idx >= Nn * 8) return;
    int n = idx >> 3, h = idx & 7;
    const float* hp = g_h1 + (size_t)n * 256 + h * 32;
    const float* asp = as_ + h * 32;
    const float* adp = ad_ + h * 32;
    float s = 0.f, d = 0.f;
    #pragma unroll
    for (int c = 0; c < 32; ++c) {
        float v = hp[c];
        s += v * asp[c];
        d += v * adp[c];
    }
    g_als1[idx] = s;
    g_ald1[idx] = d;
}

// ---------------- layer-1: fused softmax + aggregation + bias + LN + ELU ---------
__global__ void gat1_node_kernel(const float* __restrict__ b,
                                 const float* __restrict__ g,
                                 const float* __restrict__ beta) {
    const int d = blockIdx.x;
    const int t = threadIdx.x;
    const int h = t >> 5, lane = t & 31;
    const int beg = g_off[d], end = g_off[d + 1];
    const int deg = end - beg;

    __shared__ int   sh_src[128];
    __shared__ float sh_ex[128 * 8];
    __shared__ float red1[256], red2[256];

    const float ald = g_ald1[d * 8 + h];

    float mx = -INFINITY, sumrae = 0.f;
    for (int e = beg + lane; e < end; e += 32) {
        int s = g_csr_src[e], r = g_csr_type[e];
        float rv = g_rae[r * 8 + h];
        float a = g_als1[s * 8 + h] + ald + rv;
        a = a > 0.f ? a : 0.2f * a;
        mx = fmaxf(mx, a);
        sumrae += rv;
    }
    #pragma unroll
    for (int o = 16; o; o >>= 1) {
        mx = fmaxf(mx, __shfl_xor_sync(0xffffffffu, mx, o));
        sumrae += __shfl_xor_sync(0xffffffffu, sumrae, o);
    }
    float aself = g_als1[d * 8 + h] + ald + sumrae / fmaxf((float)deg, 1.f);
    aself = aself > 0.f ? aself : 0.2f * aself;
    mx = fmaxf(mx, aself);

    float exs = __expf(aself - mx);
    float acc = exs * g_h1[(size_t)d * 256 + t];
    float den = (lane == 0) ? exs : 0.f;

    for (int c0 = beg; c0 < end; c0 += 128) {
        int csz = min(128, end - c0);
        for (int j = lane; j < csz; j += 32) {
            int e = c0 + j;
            int s = g_csr_src[e], r = g_csr_type[e];
            float a = g_als1[s * 8 + h] + ald + g_rae[r * 8 + h];
            a = a > 0.f ? a : 0.2f * a;
            float ex = __expf(a - mx);
            sh_ex[j * 8 + h] = ex;
            den += ex;
            if (h == 0) sh_src[j] = s;
        }
        __syncthreads();
        for (int j = 0; j < csz; ++j)
            acc += sh_ex[j * 8 + h] * g_h1[(size_t)sh_src[j] * 256 + t];
        __syncthreads();
    }
    #pragma unroll
    for (int o = 16; o; o >>= 1) den += __shfl_xor_sync(0xffffffffu, den, o);

    float v = acc / (den + 1e-16f) + b[t];
    red1[t] = v; red2[t] = v * v;
    __syncthreads();
    #pragma unroll
    for (int o = 128; o > 0; o >>= 1) {
        if (t < o) { red1[t] += red1[t + o]; red2[t] += red2[t + o]; }
        __syncthreads();
    }
    float m = red1[0] * (1.f / 256.f);
    float var = red2[0] * (1.f / 256.f) - m * m;
    float y = (v - m) * rsqrtf(var + 1e-5f) * g[t] + beta[t];
    g_out1[(size_t)d * 256 + t] = y > 0.f ? y : expm1f(y);
}

// ---------------- layer-2 attention logits ----------------------------------------
__global__ void attn2_kernel(const float* __restrict__ as_,
                             const float* __restrict__ ad_) {
    int n = blockIdx.x, t = threadIdx.x;  // 128 threads
    float v = g_h2[(size_t)n * 128 + t];
    __shared__ float s1[128], s2[128];
    s1[t] = v * as_[t]; s2[t] = v * ad_[t];
    __syncthreads();
    #pragma unroll
    for (int off = 64; off > 0; off >>= 1) {
        if (t < off) { s1[t] += s1[t + off]; s2[t] += s2[t + off]; }
        __syncthreads();
    }
    if (t == 0) { g_als2[n] = s1[0]; g_ald2[n] = s2[0]; }
}

// ---------------- layer-2: fused softmax + aggregation + bias + LN ---------------
__global__ void gat2_node_kernel(const float* __restrict__ b,
                                 const float* __restrict__ g,
                                 const float* __restrict__ beta,
                                 float* __restrict__ out) {
    const int d = blockIdx.x;
    const int t = threadIdx.x;
    const int beg = g_off[d], end = g_off[d + 1];

    __shared__ int   sh_src[128];
    __shared__ float sh_ex[128];
    __shared__ float red1[128], red2[128];

    const float ald = g_ald2[d];

    float mx = -INFINITY;
    for (int e = beg + t; e < end; e += 128) {
        float a = g_als2[g_csr_src[e]] + ald;
        a = a > 0.f ? a : 0.2f * a;
        mx = fmaxf(mx, a);
    }
    red1[t] = mx;
    __syncthreads();
    #pragma unroll
    for (int o = 64; o > 0; o >>= 1) {
        if (t < o) red1[t] = fmaxf(red1[t], red1[t + o]);
        __syncthreads();
    }
    mx = red1[0];
    float aself = g_als2[d] + ald;
    aself = aself > 0.f ? aself : 0.2f * aself;
    mx = fmaxf(mx, aself);
    __syncthreads();

    float exs = __expf(aself - mx);
    float acc = exs * g_h2[(size_t)d * 128 + t];
    float den_p = (t == 0) ? exs : 0.f;

    for (int c0 = beg; c0 < end; c0 += 128) {
        int csz = min(128, end - c0);
        if (t < csz) {
            int e = c0 + t;
            int s = g_csr_src[e];
            float a = g_als2[s] + ald;
            a = a > 0.f ? a : 0.2f * a;
            float ex = __expf(a - mx);
            sh_ex[t] = ex;
            sh_src[t] = s;
            den_p += ex;
        }
        __syncthreads();
        for (int j = 0; j < csz; ++j)
            acc += sh_ex[j] * g_h2[(size_t)sh_src[j] * 128 + t];
        __syncthreads();
    }
    red1[t] = den_p;
    __syncthreads();
    #pragma unroll
    for (int o = 64; o > 0; o >>= 1) {
        if (t < o) red1[t] += red1[t + o];
        __syncthreads();
    }
    float den = red1[0];
    __syncthreads();

    float v = acc / (den + 1e-16f) + b[t];
    red1[t] = v; red2[t] = v * v;
    __syncthreads();
    #pragma unroll
    for (int o = 64; o > 0; o >>= 1) {
        if (t < o) { red1[t] += red1[t + o]; red2[t] += red2[t + o]; }
        __syncthreads();
    }
    float m = red1[0] * (1.f / 128.f);
    float var = red2[0] * (1.f / 128.f) - m * m;
    out[(size_t)d * 128 + t] = (v - m) * rsqrtf(var + 1e-5f) * g[t] + beta[t];
}

// ---------------- launch -----------------------------------------------------------
extern "C" void kernel_launch(void* const* d_in, const int* in_sizes, int n_in,
                              void* d_out, int out_size) {
    const float* x       = (const float*)d_in[0];
    const int*   ei      = (const int*)d_in[1];
    const int*   etype   = (const int*)d_in[2];
    const float* rel_emb = (const float*)d_in[3];
    const float* W1      = (const float*)d_in[4];
    const float* as1     = (const float*)d_in[5];
    const float* ad1     = (const float*)d_in[6];
    const float* We1     = (const float*)d_in[7];
    const float* ae1     = (const float*)d_in[8];
    const float* b1      = (const float*)d_in[9];
    const float* g1      = (const float*)d_in[10];
    const float* beta1   = (const float*)d_in[11];
    const float* W2      = (const float*)d_in[12];
    const float* as2     = (const float*)d_in[13];
    const float* ad2     = (const float*)d_in[14];
    const float* b2      = (const float*)d_in[15];
    const float* g2      = (const float*)d_in[16];
    const float* beta2   = (const float*)d_in[17];
    float* out = (float*)d_out;

    const int E = in_sizes[2];
    const int Nn = in_sizes[0] / 768;
    const int* src0 = ei;
    const int* dst0 = ei + E;
    const int nb = (Nn + 1023) / 1024;

    float *ph1, *pout1, *ph2;
    cudaGetSymbolAddress((void**)&ph1, g_h1);
    cudaGetSymbolAddress((void**)&pout1, g_out1);
    cudaGetSymbolAddress((void**)&ph2, g_h2);

    // CSR build + collapsed edge attention
    init_kernel<<<(Nn + 255) / 256, 256>>>(Nn);
    prep_kernel<<<1, 512>>>(We1, ae1, rel_emb);
    hist_kernel<<<(E + 255) / 256, 256>>>(dst0, E);
    scan_part_kernel<<<nb, 1024>>>(Nn);
    scan_tops_kernel<<<1, 64>>>(nb);
    scan_add_kernel<<<(Nn + 255) / 256, 256>>>(Nn, E);
    scatter_kernel<<<(E + 255) / 256, 256>>>(src0, dst0, etype, E);

    // GEMM1: h1 = x @ W1   [Nn,768] x [768,256]   (tf32 tensor cores)
    {
        dim3 grid((Nn + 127) / 128, 2);
        gemm_tf32_kernel<<<grid, 256>>>(x, W1, ph1, Nn, 256, 768);
    }
    attn1_kernel<<<(Nn * 8 + 255) / 256, 256>>>(as1, ad1, Nn);
    gat1_node_kernel<<<Nn, 256>>>(b1, g1, beta1);

    // GEMM2: h2 = out1 @ W2   [Nn,256] x [256,128]   (tf32 tensor cores)
    {
        dim3 grid((Nn + 127) / 128, 1);
        gemm_tf32_kernel<<<grid, 256>>>(pout1, W2, ph2, Nn, 128, 256);
    }
    attn2_kernel<<<Nn, 128>>>(as2, ad2);
    gat2_node_kernel<<<Nn, 128>>>(b2, g2, beta2, out);
}

// round 5
// speedup vs baseline: 3.0897x; 1.1468x over previous
#include <cuda_runtime.h>
#include <math.h>
#include <stdint.h>

#define NMAX 50000
#define EMAX 800000

// ---------------- scratch (static device globals) ----------------------------
__device__ float g_h1[NMAX * 256];
__device__ float g_out1[NMAX * 256];
__device__ float g_h2[NMAX * 128];
__device__ float g_als1[NMAX * 8];
__device__ float g_ald1[NMAX * 8];
__device__ float g_als2[NMAX];
__device__ float g_ald2[NMAX];
__device__ float g_rae[6 * 8];
__device__ float g_alpha1[(size_t)EMAX * 8];   // post-leaky layer-1 logits (reused for layer2)
__device__ int   g_off[NMAX + 1];
__device__ int   g_cur[NMAX];
__device__ int   g_bsum[64];
__device__ int   g_csr_src[EMAX];
__device__ int   g_csr_dst[EMAX];
__device__ int   g_csr_type[EMAX];

// ---------------- init ----------------------------------------------------------
__global__ void init_kernel(int Nn) {
    int i = blockIdx.x * blockDim.x + threadIdx.x;
    if (i < Nn) g_cur[i] = 0;
}

// ---------------- collapse edge-feature attention -------------------------------
__global__ void prep_kernel(const float* __restrict__ We1,
                            const float* __restrict__ atte,
                            const float* __restrict__ rel_emb) {
    __shared__ float sve[64 * 8];
    int t = threadIdx.x;                 // 512 threads
    int d = t >> 3, h = t & 7;
    float s = 0.f;
    #pragma unroll
    for (int c = 0; c < 32; ++c)
        s += We1[d * 256 + h * 32 + c] * atte[h * 32 + c];
    sve[t] = s;
    __syncthreads();
    if (t < 48) {
        int r = t >> 3, hh = t & 7;
        float acc = 0.f;
        #pragma unroll
        for (int dd = 0; dd < 64; ++dd)
            acc += rel_emb[r * 64 + dd] * sve[dd * 8 + hh];
        g_rae[t] = acc;
    }
}

// ---------------- CSR build ------------------------------------------------------
__global__ void hist_kernel(const int* __restrict__ dst0, int E) {
    int e = blockIdx.x * blockDim.x + threadIdx.x;
    if (e < E) atomicAdd(&g_cur[dst0[e]], 1);
}

__global__ void scan_part_kernel(int Nn) {
    __shared__ int sh[1024];
    int t = threadIdx.x;
    int i = blockIdx.x * 1024 + t;
    int v = (i < Nn) ? g_cur[i] : 0;
    sh[t] = v;
    __syncthreads();
    #pragma unroll
    for (int o = 1; o < 1024; o <<= 1) {
        int add = (t >= o) ? sh[t - o] : 0;
        __syncthreads();
        sh[t] += add;
        __syncthreads();
    }
    if (i < Nn) g_off[i] = sh[t] - v;
    if (t == 1023) g_bsum[blockIdx.x] = sh[1023];
}

__global__ void scan_tops_kernel(int nb) {
    __shared__ int sh[64];
    int t = threadIdx.x;
    int v = (t < nb) ? g_bsum[t] : 0;
    sh[t] = v;
    __syncthreads();
    #pragma unroll
    for (int o = 1; o < 64; o <<= 1) {
        int add = (t >= o) ? sh[t - o] : 0;
        __syncthreads();
        sh[t] += add;
        __syncthreads();
    }
    g_bsum[t] = sh[t] - v;
}

__global__ void scan_add_kernel(int Nn, int E) {
    int i = blockIdx.x * blockDim.x + threadIdx.x;
    if (i < Nn) {
        int o = g_off[i] + g_bsum[i >> 10];
        g_off[i] = o;
        g_cur[i] = o;
    }
    if (i == 0) g_off[Nn] = E;
}

__global__ void scatter_kernel(const int* __restrict__ src0,
                               const int* __restrict__ dst0,
                               const int* __restrict__ etype, int E) {
    int e = blockIdx.x * blockDim.x + threadIdx.x;
    if (e >= E) return;
    int d = dst0[e];
    int pos = atomicAdd(&g_cur[d], 1);
    g_csr_src[pos]  = src0[e];
    g_csr_dst[pos]  = d;
    g_csr_type[pos] = etype[e];
}

// ---------------- TF32 tensor-core GEMM, cp.async double-buffered ----------------
__device__ __forceinline__ uint32_t f2tf32(float x) {
    uint32_t r;
    asm("cvt.rna.tf32.f32 %0, %1;" : "=r"(r) : "f"(x));
    return r;
}

__device__ __forceinline__ void mma_tf32(float* c, const uint32_t* a, const uint32_t* b) {
    asm volatile(
        "mma.sync.aligned.m16n8k8.row.col.f32.tf32.tf32.f32 "
        "{%0,%1,%2,%3}, {%4,%5,%6,%7}, {%8,%9}, {%0,%1,%2,%3};"
        : "+f"(c[0]), "+f"(c[1]), "+f"(c[2]), "+f"(c[3])
        : "r"(a[0]), "r"(a[1]), "r"(a[2]), "r"(a[3]), "r"(b[0]), "r"(b[1]));
}

__device__ __forceinline__ uint32_t smem_u32(const void* p) {
    return (uint32_t)__cvta_generic_to_shared(p);
}

#define AS_LD 36   // floats; 144B rows (16B-aligned for cp.async)
#define BS_LD 132  // floats; 528B rows (16B-aligned)
#define GEMM_SMEM_BYTES ((2 * 128 * AS_LD + 2 * 32 * BS_LD) * 4)

__global__ void __launch_bounds__(256, 2)
gemm_tf32_kernel(const float* __restrict__ A, const float* __restrict__ B,
                 float* __restrict__ C, int M, int N, int K) {
    extern __shared__ float dynsmem[];
    float* AsBase = dynsmem;                       // 2 * 128 * AS_LD
    float* BsBase = dynsmem + 2 * 128 * AS_LD;     // 2 * 32 * BS_LD

    const int tid = threadIdx.x;
    const int lane = tid & 31, wid = tid >> 5;
    const int wm = (wid >> 2) * 64;
    const int wn = (wid & 3) * 32;
    const int bm0 = blockIdx.x * 128;
    const int bn0 = blockIdx.y * 128;

    const int a_r = tid >> 3;                // 0..31
    const int a_c = (tid & 7) * 4;           // 0..28
    const int b_r = tid >> 5;                // 0..7
    const int b_c = (tid & 31) * 4;          // 0..124

    float acc[4][4][4];
    #pragma unroll
    for (int i = 0; i < 4; ++i)
        #pragma unroll
        for (int j = 0; j < 4; ++j)
            #pragma unroll
            for (int k = 0; k < 4; ++k) acc[i][j][k] = 0.f;

    const int nk = K >> 5;

    auto load_stage = [&](int kt, int buf) {
        const int k0 = kt * 32;
        float* As = AsBase + buf * 128 * AS_LD;
        float* Bs = BsBase + buf * 32 * BS_LD;
        #pragma unroll
        for (int i = 0; i < 4; ++i) {
            int row = a_r + 32 * i;
            int grow = bm0 + row;
            int ok = (grow < M);
            const float* src = A + (size_t)(ok ? grow : 0) * K + k0 + a_c;
            uint32_t dst = smem_u32(&As[row * AS_LD + a_c]);
            int nb = ok ? 16 : 0;
            asm volatile("cp.async.ca.shared.global [%0], [%1], 16, %2;"
                         :: "r"(dst), "l"(src), "r"(nb));
        }
        #pragma unroll
        for (int i = 0; i < 4; ++i) {
            int row = b_r + 8 * i;
            const float* src = B + (size_t)(k0 + row) * N + bn0 + b_c;
            uint32_t dst = smem_u32(&Bs[row * BS_LD + b_c]);
            asm volatile("cp.async.ca.shared.global [%0], [%1], 16;"
                         :: "r"(dst), "l"(src));
        }
        asm volatile("cp.async.commit_group;");
    };

    load_stage(0, 0);

    for (int kt = 0; kt < nk; ++kt) {
        const int buf = kt & 1;
        if (kt + 1 < nk) load_stage(kt + 1, buf ^ 1);
        else asm volatile("cp.async.commit_group;");
        asm volatile("cp.async.wait_group 1;");
        __syncthreads();

        const float* as = AsBase + buf * 128 * AS_LD;
        const float* bs = BsBase + buf * 32 * BS_LD;
        #pragma unroll
        for (int kk = 0; kk < 4; ++kk) {
            const int kb = kk * 8;
            uint32_t afrag[4][4], bfrag[4][2];
            #pragma unroll
            for (int mt = 0; mt < 4; ++mt) {
                int r0 = wm + mt * 16 + (lane >> 2);
                int c0 = kb + (lane & 3);
                afrag[mt][0] = f2tf32(as[r0 * AS_LD + c0]);
                afrag[mt][1] = f2tf32(as[(r0 + 8) * AS_LD + c0]);
                afrag[mt][2] = f2tf32(as[r0 * AS_LD + c0 + 4]);
                afrag[mt][3] = f2tf32(as[(r0 + 8) * AS_LD + c0 + 4]);
            }
            #pragma unroll
            for (int nt = 0; nt < 4; ++nt) {
                int n0 = wn + nt * 8 + (lane >> 2);
                int kr = kb + (lane & 3);
                bfrag[nt][0] = f2tf32(bs[kr * BS_LD + n0]);
                bfrag[nt][1] = f2tf32(bs[(kr + 4) * BS_LD + n0]);
            }
            #pragma unroll
            for (int mt = 0; mt < 4; ++mt)
                #pragma unroll
                for (int nt = 0; nt < 4; ++nt)
                    mma_tf32(acc[mt][nt], afrag[mt], bfrag[nt]);
        }
        __syncthreads();
    }

    #pragma unroll
    for (int mt = 0; mt < 4; ++mt) {
        int row0 = bm0 + wm + mt * 16 + (lane >> 2);
        #pragma unroll
        for (int nt = 0; nt < 4; ++nt) {
            int col0 = bn0 + wn + nt * 8 + (lane & 3) * 2;
            if (row0 < M)
                *reinterpret_cast<float2*>(C + (size_t)row0 * N + col0) =
                    make_float2(acc[mt][nt][0], acc[mt][nt][1]);
            if (row0 + 8 < M)
                *reinterpret_cast<float2*>(C + (size_t)(row0 + 8) * N + col0) =
                    make_float2(acc[mt][nt][2], acc[mt][nt][3]);
        }
    }
}

// ---------------- node attention logits (layer 1) --------------------------------
__global__ void attn1_kernel(const float* __restrict__ as_,
                             const float* __restrict__ ad_, int Nn) {
    int idx = blockIdx.x * blockDim.x + threadIdx.x;
    if (idx >= Nn * 8) return;
    int n = idx >> 3, h = idx & 7;
    const float* hp = g_h1 + (size_t)n * 256 + h * 32;
    const float* asp = as_ + h * 32;
    const float* adp = ad_ + h * 32;
    float s = 0.f, d = 0.f;
    #pragma unroll
    for (int c = 0; c < 32; ++c) {
        float v = hp[c];
        s += v * asp[c];
        d += v * adp[c];
    }
    g_als1[idx] = s;
    g_ald1[idx] = d;
}

// ---------------- layer-1 edge logits, edge-major/head-minor ---------------------
__global__ void alpha1_kernel(int E) {
    int idx = blockIdx.x * blockDim.x + threadIdx.x;
    if (idx >= E * 8) return;
    int e = idx >> 3, h = idx & 7;
    int s = g_csr_src[e];
    int d = g_csr_dst[e];
    int r = g_csr_type[e];
    float a = g_als1[s * 8 + h] + g_ald1[d * 8 + h] + g_rae[r * 8 + h];
    g_alpha1[idx] = a > 0.f ? a : 0.2f * a;
}

// ---------------- layer-1: fused softmax + aggregation + bias + LN + ELU ---------
__global__ void gat1_node_kernel(const float* __restrict__ b,
                                 const float* __restrict__ g,
                                 const float* __restrict__ beta) {
    const int d = blockIdx.x;
    const int t = threadIdx.x;               // 256
    const int h = t >> 5;                    // aggregation head (channel block)
    const int e8 = t >> 3, h8 = t & 7;       // logit-phase mapping
    const int beg = g_off[d], end = g_off[d + 1];
    const int deg = end - beg;

    __shared__ int   sh_src[128];
    __shared__ float sh_ex[128 * 8];
    __shared__ float red1[256], red2[256];
    __shared__ float sh_rae[48];
    __shared__ float sh_mx[8], sh_exs[8];

    if (t < 48) sh_rae[t] = g_rae[t];
    __syncthreads();

    // Pass A: per-head max over post-leaky logits, per-head sum of rae
    float mx = -INFINITY, sumrae = 0.f;
    for (int e0 = beg; e0 < end; e0 += 32) {
        int j = e0 + e8;
        if (j < end) {
            mx = fmaxf(mx, g_alpha1[(size_t)j * 8 + h8]);
            sumrae += sh_rae[g_csr_type[j] * 8 + h8];
        }
    }
    red1[t] = mx; red2[t] = sumrae;
    __syncthreads();
    #pragma unroll
    for (int o = 128; o >= 8; o >>= 1) {
        if (t < o) { red1[t] = fmaxf(red1[t], red1[t + o]); red2[t] += red2[t + o]; }
        __syncthreads();
    }
    if (t < 8) {
        float asf = g_als1[d * 8 + t] + g_ald1[d * 8 + t] + red2[t] / fmaxf((float)deg, 1.f);
        asf = asf > 0.f ? asf : 0.2f * asf;
        float m = fmaxf(red1[t], asf);
        sh_mx[t] = m;
        sh_exs[t] = __expf(asf - m);
    }
    __syncthreads();

    float acc = sh_exs[h] * g_h1[(size_t)d * 256 + t];
    float denp = 0.f;

    // Pass B: chunked exp + weighted gather-accumulate
    for (int c0 = beg; c0 < end; c0 += 128) {
        int csz = min(128, end - c0);
        if (t < csz) sh_src[t] = g_csr_src[c0 + t];
        for (int s0 = 0; s0 < csz; s0 += 32) {
            int j = s0 + e8;
            if (j < csz) {
                float ex = __expf(g_alpha1[(size_t)(c0 + j) * 8 + h8] - sh_mx[h8]);
                sh_ex[j * 8 + h8] = ex;
                denp += ex;
            }
        }
        __syncthreads();
        for (int j = 0; j < csz; ++j)
            acc += sh_ex[j * 8 + h] * g_h1[(size_t)sh_src[j] * 256 + t];
        __syncthreads();
    }

    red1[t] = denp;
    __syncthreads();
    #pragma unroll
    for (int o = 128; o >= 8; o >>= 1) {
        if (t < o) red1[t] += red1[t + o];
        __syncthreads();
    }
    float den = red1[h] + sh_exs[h];
    __syncthreads();

    // bias + LayerNorm + ELU
    float v = acc / (den + 1e-16f) + b[t];
    red1[t] = v; red2[t] = v * v;
    __syncthreads();
    #pragma unroll
    for (int o = 128; o > 0; o >>= 1) {
        if (t < o) { red1[t] += red1[t + o]; red2[t] += red2[t + o]; }
        __syncthreads();
    }
    float m = red1[0] * (1.f / 256.f);
    float var = red2[0] * (1.f / 256.f) - m * m;
    float y = (v - m) * rsqrtf(var + 1e-5f) * g[t] + beta[t];
    g_out1[(size_t)d * 256 + t] = y > 0.f ? y : expm1f(y);
}

// ---------------- layer-2 attention logits ----------------------------------------
__global__ void attn2_kernel(const float* __restrict__ as_,
                             const float* __restrict__ ad_) {
    int n = blockIdx.x, t = threadIdx.x;  // 128
    float v = g_h2[(size_t)n * 128 + t];
    __shared__ float s1[128], s2[128];
    s1[t] = v * as_[t]; s2[t] = v * ad_[t];
    __syncthreads();
    #pragma unroll
    for (int off = 64; off > 0; off >>= 1) {
        if (t < off) { s1[t] += s1[t + off]; s2[t] += s2[t + off]; }
        __syncthreads();
    }
    if (t == 0) { g_als2[n] = s1[0]; g_ald2[n] = s2[0]; }
}

// alpha2s[e] = als2[src[e]]  (coalesce the scattered src gathers once)
__global__ void alpha2_kernel(int E) {
    int e = blockIdx.x * blockDim.x + threadIdx.x;
    if (e < E) g_alpha1[e] = g_als2[g_csr_src[e]];
}

// ---------------- layer-2: fused softmax + aggregation + bias + LN ---------------
__global__ void gat2_node_kernel(const float* __restrict__ b,
                                 const float* __restrict__ g,
                                 const float* __restrict__ beta,
                                 float* __restrict__ out) {
    const int d = blockIdx.x;
    const int t = threadIdx.x;   // 128
    const int beg = g_off[d], end = g_off[d + 1];

    __shared__ int   sh_src[128];
    __shared__ float sh_ex[128];
    __shared__ float red1[128], red2[128];

    const float ald = g_ald2[d];

    float mx = -INFINITY;
    for (int e = beg + t; e < end; e += 128) {
        float a = g_alpha1[e] + ald;
        a = a > 0.f ? a : 0.2f * a;
        mx = fmaxf(mx, a);
    }
    red1[t] = mx;
    __syncthreads();
    #pragma unroll
    for (int o = 64; o > 0; o >>= 1) {
        if (t < o) red1[t] = fmaxf(red1[t], red1[t + o]);
        __syncthreads();
    }
    mx = red1[0];
    float aself = g_als2[d] + ald;
    aself = aself > 0.f ? aself : 0.2f * aself;
    mx = fmaxf(mx, aself);
    __syncthreads();

    float exs = __expf(aself - mx);
    float acc = exs * g_h2[(size_t)d * 128 + t];
    float den_p = (t == 0) ? exs : 0.f;

    for (int c0 = beg; c0 < end; c0 += 128) {
        int csz = min(128, end - c0);
        if (t < csz) {
            float a = g_alpha1[c0 + t] + ald;
            a = a > 0.f ? a : 0.2f * a;
            float ex = __expf(a - mx);
            sh_ex[t] = ex;
            sh_src[t] = g_csr_src[c0 + t];
            den_p += ex;
        }
        __syncthreads();
        for (int j = 0; j < csz; ++j)
            acc += sh_ex[j] * g_h2[(size_t)sh_src[j] * 128 + t];
        __syncthreads();
    }
    red1[t] = den_p;
    __syncthreads();
    #pragma unroll
    for (int o = 64; o > 0; o >>= 1) {
        if (t < o) red1[t] += red1[t + o];
        __syncthreads();
    }
    float den = red1[0];
    __syncthreads();

    float v = acc / (den + 1e-16f) + b[t];
    red1[t] = v; red2[t] = v * v;
    __syncthreads();
    #pragma unroll
    for (int o = 64; o > 0; o >>= 1) {
        if (t < o) { red1[t] += red1[t + o]; red2[t] += red2[t + o]; }
        __syncthreads();
    }
    float m = red1[0] * (1.f / 128.f);
    float var = red2[0] * (1.f / 128.f) - m * m;
    out[(size_t)d * 128 + t] = (v - m) * rsqrtf(var + 1e-5f) * g[t] + beta[t];
}

// ---------------- launch -----------------------------------------------------------
extern "C" void kernel_launch(void* const* d_in, const int* in_sizes, int n_in,
                              void* d_out, int out_size) {
    const float* x       = (const float*)d_in[0];
    const int*   ei      = (const int*)d_in[1];
    const int*   etype   = (const int*)d_in[2];
    const float* rel_emb = (const float*)d_in[3];
    const float* W1      = (const float*)d_in[4];
    const float* as1     = (const float*)d_in[5];
    const float* ad1     = (const float*)d_in[6];
    const float* We1     = (const float*)d_in[7];
    const float* ae1     = (const float*)d_in[8];
    const float* b1      = (const float*)d_in[9];
    const float* g1      = (const float*)d_in[10];
    const float* beta1   = (const float*)d_in[11];
    const float* W2      = (const float*)d_in[12];
    const float* as2     = (const float*)d_in[13];
    const float* ad2     = (const float*)d_in[14];
    const float* b2      = (const float*)d_in[15];
    const float* g2      = (const float*)d_in[16];
    const float* beta2   = (const float*)d_in[17];
    float* out = (float*)d_out;

    const int E = in_sizes[2];
    const int Nn = in_sizes[0] / 768;
    const int* src0 = ei;
    const int* dst0 = ei + E;
    const int nb = (Nn + 1023) / 1024;

    float *ph1, *pout1, *ph2;
    cudaGetSymbolAddress((void**)&ph1, g_h1);
    cudaGetSymbolAddress((void**)&pout1, g_out1);
    cudaGetSymbolAddress((void**)&ph2, g_h2);

    static int smem_configured = 0;
    if (!smem_configured) {
        cudaFuncSetAttribute(gemm_tf32_kernel,
                             cudaFuncAttributeMaxDynamicSharedMemorySize,
                             GEMM_SMEM_BYTES);
        smem_configured = 1;
    }

    // CSR build + collapsed edge attention
    init_kernel<<<(Nn + 255) / 256, 256>>>(Nn);
    prep_kernel<<<1, 512>>>(We1, ae1, rel_emb);
    hist_kernel<<<(E + 255) / 256, 256>>>(dst0, E);
    scan_part_kernel<<<nb, 1024>>>(Nn);
    scan_tops_kernel<<<1, 64>>>(nb);
    scan_add_kernel<<<(Nn + 255) / 256, 256>>>(Nn, E);
    scatter_kernel<<<(E + 255) / 256, 256>>>(src0, dst0, etype, E);

    // GEMM1: h1 = x @ W1   [Nn,768] x [768,256]
    {
        dim3 grid((Nn + 127) / 128, 2);
        gemm_tf32_kernel<<<grid, 256, GEMM_SMEM_BYTES>>>(x, W1, ph1, Nn, 256, 768);
    }
    attn1_kernel<<<(Nn * 8 + 255) / 256, 256>>>(as1, ad1, Nn);
    alpha1_kernel<<<(E * 8 + 255) / 256, 256>>>(E);
    gat1_node_kernel<<<Nn, 256>>>(b1, g1, beta1);

    // GEMM2: h2 = out1 @ W2   [Nn,256] x [256,128]
    {
        dim3 grid((Nn + 127) / 128, 1);
        gemm_tf32_kernel<<<grid, 256, GEMM_SMEM_BYTES>>>(pout1, W2, ph2, Nn, 128, 256);
    }
    attn2_kernel<<<Nn, 128>>>(as2, ad2);
    alpha2_kernel<<<(E + 255) / 256, 256>>>(E);
    gat2_node_kernel<<<Nn, 128>>>(b2, g2, beta2, out);
}

// round 6
// speedup vs baseline: 3.4002x; 1.1005x over previous
#include <cuda_runtime.h>
#include <math.h>
#include <stdint.h>

#define NMAX 50000
#define EMAX 800000

// ---------------- scratch (static device globals) ----------------------------
__device__ float g_h1[NMAX * 256];
__device__ float g_out1[NMAX * 256];
__device__ float g_h2[NMAX * 128];
__device__ float g_als1[NMAX * 8];
__device__ float g_ald1[NMAX * 8];
__device__ float g_als2[NMAX];
__device__ float g_ald2[NMAX];
__device__ float g_rae[6 * 8];
__device__ int   g_off[NMAX + 1];
__device__ int   g_cur[NMAX];
__device__ int   g_bsum[64];
__device__ int   g_csr_pack[EMAX];     // src | (type << 20)

// ---------------- init ----------------------------------------------------------
__global__ void init_kernel(int Nn) {
    int i = blockIdx.x * blockDim.x + threadIdx.x;
    if (i < Nn) g_cur[i] = 0;
}

// ---------------- collapse edge-feature attention -------------------------------
__global__ void prep_kernel(const float* __restrict__ We1,
                            const float* __restrict__ atte,
                            const float* __restrict__ rel_emb) {
    __shared__ float sve[64 * 8];
    int t = threadIdx.x;                 // 512 threads
    int d = t >> 3, h = t & 7;
    float s = 0.f;
    #pragma unroll
    for (int c = 0; c < 32; ++c)
        s += We1[d * 256 + h * 32 + c] * atte[h * 32 + c];
    sve[t] = s;
    __syncthreads();
    if (t < 48) {
        int r = t >> 3, hh = t & 7;
        float acc = 0.f;
        #pragma unroll
        for (int dd = 0; dd < 64; ++dd)
            acc += rel_emb[r * 64 + dd] * sve[dd * 8 + hh];
        g_rae[t] = acc;
    }
}

// ---------------- CSR build ------------------------------------------------------
__global__ void hist_kernel(const int* __restrict__ dst0, int E) {
    int e = blockIdx.x * blockDim.x + threadIdx.x;
    if (e < E) atomicAdd(&g_cur[dst0[e]], 1);
}

__global__ void scan_part_kernel(int Nn) {
    __shared__ int sh[1024];
    int t = threadIdx.x;
    int i = blockIdx.x * 1024 + t;
    int v = (i < Nn) ? g_cur[i] : 0;
    sh[t] = v;
    __syncthreads();
    #pragma unroll
    for (int o = 1; o < 1024; o <<= 1) {
        int add = (t >= o) ? sh[t - o] : 0;
        __syncthreads();
        sh[t] += add;
        __syncthreads();
    }
    if (i < Nn) g_off[i] = sh[t] - v;
    if (t == 1023) g_bsum[blockIdx.x] = sh[1023];
}

__global__ void scan_tops_kernel(int nb) {
    __shared__ int sh[64];
    int t = threadIdx.x;
    int v = (t < nb) ? g_bsum[t] : 0;
    sh[t] = v;
    __syncthreads();
    #pragma unroll
    for (int o = 1; o < 64; o <<= 1) {
        int add = (t >= o) ? sh[t - o] : 0;
        __syncthreads();
        sh[t] += add;
        __syncthreads();
    }
    g_bsum[t] = sh[t] - v;
}

__global__ void scan_add_kernel(int Nn, int E) {
    int i = blockIdx.x * blockDim.x + threadIdx.x;
    if (i < Nn) {
        int o = g_off[i] + g_bsum[i >> 10];
        g_off[i] = o;
        g_cur[i] = o;
    }
    if (i == 0) g_off[Nn] = E;
}

__global__ void scatter_kernel(const int* __restrict__ src0,
                               const int* __restrict__ dst0,
                               const int* __restrict__ etype, int E) {
    int e = blockIdx.x * blockDim.x + threadIdx.x;
    if (e >= E) return;
    int d = dst0[e];
    int pos = atomicAdd(&g_cur[d], 1);
    g_csr_pack[pos] = src0[e] | (etype[e] << 20);
}

// ---------------- TF32 tensor-core GEMM, cp.async double-buffered ----------------
__device__ __forceinline__ uint32_t f2tf32(float x) {
    uint32_t r;
    asm("cvt.rna.tf32.f32 %0, %1;" : "=r"(r) : "f"(x));
    return r;
}

__device__ __forceinline__ void mma_tf32(float* c, const uint32_t* a, const uint32_t* b) {
    asm volatile(
        "mma.sync.aligned.m16n8k8.row.col.f32.tf32.tf32.f32 "
        "{%0,%1,%2,%3}, {%4,%5,%6,%7}, {%8,%9}, {%0,%1,%2,%3};"
        : "+f"(c[0]), "+f"(c[1]), "+f"(c[2]), "+f"(c[3])
        : "r"(a[0]), "r"(a[1]), "r"(a[2]), "r"(a[3]), "r"(b[0]), "r"(b[1]));
}

__device__ __forceinline__ uint32_t smem_u32(const void* p) {
    return (uint32_t)__cvta_generic_to_shared(p);
}

#define AS_LD 36
#define BS_LD 132
#define GEMM_SMEM_BYTES ((2 * 128 * AS_LD + 2 * 32 * BS_LD) * 4)

__global__ void __launch_bounds__(256, 2)
gemm_tf32_kernel(const float* __restrict__ A, const float* __restrict__ B,
                 float* __restrict__ C, int M, int N, int K) {
    extern __shared__ float dynsmem[];
    float* AsBase = dynsmem;
    float* BsBase = dynsmem + 2 * 128 * AS_LD;

    const int tid = threadIdx.x;
    const int lane = tid & 31, wid = tid >> 5;
    const int wm = (wid >> 2) * 64;
    const int wn = (wid & 3) * 32;
    const int bm0 = blockIdx.x * 128;
    const int bn0 = blockIdx.y * 128;

    const int a_r = tid >> 3;
    const int a_c = (tid & 7) * 4;
    const int b_r = tid >> 5;
    const int b_c = (tid & 31) * 4;

    float acc[4][4][4];
    #pragma unroll
    for (int i = 0; i < 4; ++i)
        #pragma unroll
        for (int j = 0; j < 4; ++j)
            #pragma unroll
            for (int k = 0; k < 4; ++k) acc[i][j][k] = 0.f;

    const int nk = K >> 5;

    auto load_stage = [&](int kt, int buf) {
        const int k0 = kt * 32;
        float* As = AsBase + buf * 128 * AS_LD;
        float* Bs = BsBase + buf * 32 * BS_LD;
        #pragma unroll
        for (int i = 0; i < 4; ++i) {
            int row = a_r + 32 * i;
            int grow = bm0 + row;
            int ok = (grow < M);
            const float* src = A + (size_t)(ok ? grow : 0) * K + k0 + a_c;
            uint32_t dst = smem_u32(&As[row * AS_LD + a_c]);
            int nb = ok ? 16 : 0;
            asm volatile("cp.async.ca.shared.global [%0], [%1], 16, %2;"
                         :: "r"(dst), "l"(src), "r"(nb));
        }
        #pragma unroll
        for (int i = 0; i < 4; ++i) {
            int row = b_r + 8 * i;
            const float* src = B + (size_t)(k0 + row) * N + bn0 + b_c;
            uint32_t dst = smem_u32(&Bs[row * BS_LD + b_c]);
            asm volatile("cp.async.ca.shared.global [%0], [%1], 16;"
                         :: "r"(dst), "l"(src));
        }
        asm volatile("cp.async.commit_group;");
    };

    load_stage(0, 0);

    for (int kt = 0; kt < nk; ++kt) {
        const int buf = kt & 1;
        if (kt + 1 < nk) load_stage(kt + 1, buf ^ 1);
        else asm volatile("cp.async.commit_group;");
        asm volatile("cp.async.wait_group 1;");
        __syncthreads();

        const float* as = AsBase + buf * 128 * AS_LD;
        const float* bs = BsBase + buf * 32 * BS_LD;
        #pragma unroll
        for (int kk = 0; kk < 4; ++kk) {
            const int kb = kk * 8;
            uint32_t afrag[4][4], bfrag[4][2];
            #pragma unroll
            for (int mt = 0; mt < 4; ++mt) {
                int r0 = wm + mt * 16 + (lane >> 2);
                int c0 = kb + (lane & 3);
                afrag[mt][0] = f2tf32(as[r0 * AS_LD + c0]);
                afrag[mt][1] = f2tf32(as[(r0 + 8) * AS_LD + c0]);
                afrag[mt][2] = f2tf32(as[r0 * AS_LD + c0 + 4]);
                afrag[mt][3] = f2tf32(as[(r0 + 8) * AS_LD + c0 + 4]);
            }
            #pragma unroll
            for (int nt = 0; nt < 4; ++nt) {
                int n0 = wn + nt * 8 + (lane >> 2);
                int kr = kb + (lane & 3);
                bfrag[nt][0] = f2tf32(bs[kr * BS_LD + n0]);
                bfrag[nt][1] = f2tf32(bs[(kr + 4) * BS_LD + n0]);
            }
            #pragma unroll
            for (int mt = 0; mt < 4; ++mt)
                #pragma unroll
                for (int nt = 0; nt < 4; ++nt)
                    mma_tf32(acc[mt][nt], afrag[mt], bfrag[nt]);
        }
        __syncthreads();
    }

    #pragma unroll
    for (int mt = 0; mt < 4; ++mt) {
        int row0 = bm0 + wm + mt * 16 + (lane >> 2);
        #pragma unroll
        for (int nt = 0; nt < 4; ++nt) {
            int col0 = bn0 + wn + nt * 8 + (lane & 3) * 2;
            if (row0 < M)
                *reinterpret_cast<float2*>(C + (size_t)row0 * N + col0) =
                    make_float2(acc[mt][nt][0], acc[mt][nt][1]);
            if (row0 + 8 < M)
                *reinterpret_cast<float2*>(C + (size_t)(row0 + 8) * N + col0) =
                    make_float2(acc[mt][nt][2], acc[mt][nt][3]);
        }
    }
}

// ---------------- node attention logits (layer 1) --------------------------------
__global__ void attn1_kernel(const float* __restrict__ as_,
                             const float* __restrict__ ad_, int Nn) {
    int idx = blockIdx.x * blockDim.x + threadIdx.x;
    if (idx >= Nn * 8) return;
    int n = idx >> 3, h = idx & 7;
    const float* hp = g_h1 + (size_t)n * 256 + h * 32;
    const float* asp = as_ + h * 32;
    const float* adp = ad_ + h * 32;
    float s = 0.f, d = 0.f;
    #pragma unroll
    for (int c = 0; c < 32; ++c) {
        float v = hp[c];
        s += v * asp[c];
        d += v * adp[c];
    }
    g_als1[idx] = s;
    g_ald1[idx] = d;
}

// ---------------- layer-1: single-pass softmax+aggregate+bias+LN+ELU -------------
// No max subtraction: weights exp(a)/sum exp(a) are identical; |a| <~ 8 so exp is
// safe in fp32. One block (256 thr) per dst node.
__global__ void gat1_node_kernel(const float* __restrict__ b,
                                 const float* __restrict__ g,
                                 const float* __restrict__ beta) {
    const int d = blockIdx.x;
    const int t = threadIdx.x;               // 256
    const int h = t >> 5;                    // aggregation head (channel block)
    const int e8 = t >> 3, h8 = t & 7;       // logit-phase mapping
    const int beg = g_off[d], end = g_off[d + 1];
    const int deg = end - beg;

    __shared__ int   sh_pack[128];
    __shared__ float sh_ex[128 * 8];
    __shared__ float red1[256], red2[256];
    __shared__ float sh_rae[48];
    __shared__ float sh_den[8], sh_exs[8];

    if (t < 48) sh_rae[t] = g_rae[t];
    const float ald = g_ald1[d * 8 + h8];
    __syncthreads();

    float acc = 0.f, denp = 0.f, sumrae = 0.f;

    for (int c0 = beg; c0 < end; c0 += 128) {
        int csz = min(128, end - c0);
        if (t < csz) sh_pack[t] = g_csr_pack[c0 + t];
        __syncthreads();
        // logits + exp for this chunk (edge-major, head-minor: coalesced als reads)
        for (int s0 = 0; s0 < csz; s0 += 32) {
            int j = s0 + e8;
            if (j < csz) {
                int p = sh_pack[j];
                int s = p & 0xFFFFF, r = p >> 20;
                float rv = sh_rae[r * 8 + h8];
                float a = g_als1[s * 8 + h8] + ald + rv;
                a = a > 0.f ? a : 0.2f * a;
                float ex = __expf(a);
                sh_ex[j * 8 + h8] = ex;
                denp += ex;
                sumrae += rv;
            }
        }
        __syncthreads();
        // weighted gather-accumulate, 2 accumulators for MLP
        {
            float a0 = 0.f, a1 = 0.f;
            int j = 0;
            for (; j + 2 <= csz; j += 2) {
                int s0i = sh_pack[j] & 0xFFFFF;
                int s1i = sh_pack[j + 1] & 0xFFFFF;
                a0 += sh_ex[j * 8 + h] * g_h1[(size_t)s0i * 256 + t];
                a1 += sh_ex[(j + 1) * 8 + h] * g_h1[(size_t)s1i * 256 + t];
            }
            if (j < csz)
                a0 += sh_ex[j * 8 + h] * g_h1[(size_t)(sh_pack[j] & 0xFFFFF) * 256 + t];
            acc += a0 + a1;
        }
        __syncthreads();
    }

    // per-head reductions (head = t & 7; strides are multiples of 8)
    red1[t] = denp; red2[t] = sumrae;
    __syncthreads();
    #pragma unroll
    for (int o = 128; o >= 8; o >>= 1) {
        if (t < o) { red1[t] += red1[t + o]; red2[t] += red2[t + o]; }
        __syncthreads();
    }
    if (t < 8) {
        float asf = g_als1[d * 8 + t] + g_ald1[d * 8 + t] + red2[t] / fmaxf((float)deg, 1.f);
        asf = asf > 0.f ? asf : 0.2f * asf;
        float exs = __expf(asf);
        sh_exs[t] = exs;
        sh_den[t] = red1[t] + exs;
    }
    __syncthreads();

    acc += sh_exs[h] * g_h1[(size_t)d * 256 + t];

    // bias + LayerNorm + ELU
    float v = acc / (sh_den[h] + 1e-16f) + b[t];
    red1[t] = v; red2[t] = v * v;
    __syncthreads();
    #pragma unroll
    for (int o = 128; o > 0; o >>= 1) {
        if (t < o) { red1[t] += red1[t + o]; red2[t] += red2[t + o]; }
        __syncthreads();
    }
    float m = red1[0] * (1.f / 256.f);
    float var = red2[0] * (1.f / 256.f) - m * m;
    float y = (v - m) * rsqrtf(var + 1e-5f) * g[t] + beta[t];
    g_out1[(size_t)d * 256 + t] = y > 0.f ? y : expm1f(y);
}

// ---------------- layer-2 attention logits ----------------------------------------
__global__ void attn2_kernel(const float* __restrict__ as_,
                             const float* __restrict__ ad_) {
    int n = blockIdx.x, t = threadIdx.x;  // 128
    float v = g_h2[(size_t)n * 128 + t];
    __shared__ float s1[128], s2[128];
    s1[t] = v * as_[t]; s2[t] = v * ad_[t];
    __syncthreads();
    #pragma unroll
    for (int off = 64; off > 0; off >>= 1) {
        if (t < off) { s1[t] += s1[t + off]; s2[t] += s2[t + off]; }
        __syncthreads();
    }
    if (t == 0) { g_als2[n] = s1[0]; g_ald2[n] = s2[0]; }
}

// ---------------- layer-2: single-pass softmax+aggregate+bias+LN -----------------
__global__ void gat2_node_kernel(const float* __restrict__ b,
                                 const float* __restrict__ g,
                                 const float* __restrict__ beta,
                                 float* __restrict__ out) {
    const int d = blockIdx.x;
    const int t = threadIdx.x;   // 128
    const int beg = g_off[d], end = g_off[d + 1];

    __shared__ int   sh_src[128];
    __shared__ float sh_ex[128];
    __shared__ float red1[128], red2[128];

    const float ald = g_ald2[d];

    float acc = 0.f, denp = 0.f;

    for (int c0 = beg; c0 < end; c0 += 128) {
        int csz = min(128, end - c0);
        if (t < csz) {
            int s = g_csr_pack[c0 + t] & 0xFFFFF;
            float a = g_als2[s] + ald;
            a = a > 0.f ? a : 0.2f * a;
            float ex = __expf(a);
            sh_ex[t] = ex;
            sh_src[t] = s;
            denp += ex;
        }
        __syncthreads();
        {
            float a0 = 0.f, a1 = 0.f;
            int j = 0;
            for (; j + 2 <= csz; j += 2) {
                a0 += sh_ex[j] * g_h2[(size_t)sh_src[j] * 128 + t];
                a1 += sh_ex[j + 1] * g_h2[(size_t)sh_src[j + 1] * 128 + t];
            }
            if (j < csz) a0 += sh_ex[j] * g_h2[(size_t)sh_src[j] * 128 + t];
            acc += a0 + a1;
        }
        __syncthreads();
    }

    red1[t] = denp;
    __syncthreads();
    #pragma unroll
    for (int o = 64; o > 0; o >>= 1) {
        if (t < o) red1[t] += red1[t + o];
        __syncthreads();
    }
    float aself = g_als2[d] + ald;
    aself = aself > 0.f ? aself : 0.2f * aself;
    float exs = __expf(aself);
    float den = red1[0] + exs;
    acc += exs * g_h2[(size_t)d * 128 + t];
    __syncthreads();

    float v = acc / (den + 1e-16f) + b[t];
    red1[t] = v; red2[t] = v * v;
    __syncthreads();
    #pragma unroll
    for (int o = 64; o > 0; o >>= 1) {
        if (t < o) { red1[t] += red1[t + o]; red2[t] += red2[t + o]; }
        __syncthreads();
    }
    float m = red1[0] * (1.f / 128.f);
    float var = red2[0] * (1.f / 128.f) - m * m;
    out[(size_t)d * 128 + t] = (v - m) * rsqrtf(var + 1e-5f) * g[t] + beta[t];
}

// ---------------- launch -----------------------------------------------------------
extern "C" void kernel_launch(void* const* d_in, const int* in_sizes, int n_in,
                              void* d_out, int out_size) {
    const float* x       = (const float*)d_in[0];
    const int*   ei      = (const int*)d_in[1];
    const int*   etype   = (const int*)d_in[2];
    const float* rel_emb = (const float*)d_in[3];
    const float* W1      = (const float*)d_in[4];
    const float* as1     = (const float*)d_in[5];
    const float* ad1     = (const float*)d_in[6];
    const float* We1     = (const float*)d_in[7];
    const float* ae1     = (const float*)d_in[8];
    const float* b1      = (const float*)d_in[9];
    const float* g1      = (const float*)d_in[10];
    const float* beta1   = (const float*)d_in[11];
    const float* W2      = (const float*)d_in[12];
    const float* as2     = (const float*)d_in[13];
    const float* ad2     = (const float*)d_in[14];
    const float* b2      = (const float*)d_in[15];
    const float* g2      = (const float*)d_in[16];
    const float* beta2   = (const float*)d_in[17];
    float* out = (float*)d_out;

    const int E = in_sizes[2];
    const int Nn = in_sizes[0] / 768;
    const int* src0 = ei;
    const int* dst0 = ei + E;
    const int nb = (Nn + 1023) / 1024;

    float *ph1, *pout1, *ph2;
    cudaGetSymbolAddress((void**)&ph1, g_h1);
    cudaGetSymbolAddress((void**)&pout1, g_out1);
    cudaGetSymbolAddress((void**)&ph2, g_h2);

    static int smem_configured = 0;
    if (!smem_configured) {
        cudaFuncSetAttribute(gemm_tf32_kernel,
                             cudaFuncAttributeMaxDynamicSharedMemorySize,
                             GEMM_SMEM_BYTES);
        smem_configured = 1;
    }

    // CSR build + collapsed edge attention
    init_kernel<<<(Nn + 255) / 256, 256>>>(Nn);
    prep_kernel<<<1, 512>>>(We1, ae1, rel_emb);
    hist_kernel<<<(E + 255) / 256, 256>>>(dst0, E);
    scan_part_kernel<<<nb, 1024>>>(Nn);
    scan_tops_kernel<<<1, 64>>>(nb);
    scan_add_kernel<<<(Nn + 255) / 256, 256>>>(Nn, E);
    scatter_kernel<<<(E + 255) / 256, 256>>>(src0, dst0, etype, E);

    // GEMM1: h1 = x @ W1   [Nn,768] x [768,256]
    {
        dim3 grid((Nn + 127) / 128, 2);
        gemm_tf32_kernel<<<grid, 256, GEMM_SMEM_BYTES>>>(x, W1, ph1, Nn, 256, 768);
    }
    attn1_kernel<<<(Nn * 8 + 255) / 256, 256>>>(as1, ad1, Nn);
    gat1_node_kernel<<<Nn, 256>>>(b1, g1, beta1);

    // GEMM2: h2 = out1 @ W2   [Nn,256] x [256,128]
    {
        dim3 grid((Nn + 127) / 128, 1);
        gemm_tf32_kernel<<<grid, 256, GEMM_SMEM_BYTES>>>(pout1, W2, ph2, Nn, 128, 256);
    }
    attn2_kernel<<<Nn, 128>>>(as2, ad2);
    gat2_node_kernel<<<Nn, 128>>>(b2, g2, beta2, out);
}

// round 7
// speedup vs baseline: 5.1711x; 1.5208x over previous
#include <cuda_runtime.h>
#include <math.h>
#include <stdint.h>

#define NMAX 50000
#define EMAX 800000

// ---------------- scratch (static device globals) ----------------------------
__device__ float g_h1[NMAX * 256];
__device__ float g_out1[NMAX * 256];
__device__ float g_h2[NMAX * 128];
__device__ float g_als1[NMAX * 8];
__device__ float g_ald1[NMAX * 8];
__device__ float g_als2[NMAX];
__device__ float g_ald2[NMAX];
__device__ float g_rae[6 * 8];
__device__ int   g_off[NMAX + 1];
__device__ int   g_cur[NMAX];
__device__ int   g_bsum[64];
__device__ int   g_csr_pack[EMAX];     // src | (type << 20)

// ---------------- init ----------------------------------------------------------
__global__ void init_kernel(int Nn) {
    int i = blockIdx.x * blockDim.x + threadIdx.x;
    if (i < Nn) g_cur[i] = 0;
}

// ---------------- collapse edge-feature attention -------------------------------
__global__ void prep_kernel(const float* __restrict__ We1,
                            const float* __restrict__ atte,
                            const float* __restrict__ rel_emb) {
    __shared__ float sve[64 * 8];
    int t = threadIdx.x;                 // 512 threads
    int d = t >> 3, h = t & 7;
    float s = 0.f;
    #pragma unroll
    for (int c = 0; c < 32; ++c)
        s += We1[d * 256 + h * 32 + c] * atte[h * 32 + c];
    sve[t] = s;
    __syncthreads();
    if (t < 48) {
        int r = t >> 3, hh = t & 7;
        float acc = 0.f;
        #pragma unroll
        for (int dd = 0; dd < 64; ++dd)
            acc += rel_emb[r * 64 + dd] * sve[dd * 8 + hh];
        g_rae[t] = acc;
    }
}

// ---------------- CSR build ------------------------------------------------------
__global__ void hist_kernel(const int* __restrict__ dst0, int E) {
    int e = blockIdx.x * blockDim.x + threadIdx.x;
    if (e < E) atomicAdd(&g_cur[dst0[e]], 1);
}

__global__ void scan_part_kernel(int Nn) {
    __shared__ int sh[1024];
    int t = threadIdx.x;
    int i = blockIdx.x * 1024 + t;
    int v = (i < Nn) ? g_cur[i] : 0;
    sh[t] = v;
    __syncthreads();
    #pragma unroll
    for (int o = 1; o < 1024; o <<= 1) {
        int add = (t >= o) ? sh[t - o] : 0;
        __syncthreads();
        sh[t] += add;
        __syncthreads();
    }
    if (i < Nn) g_off[i] = sh[t] - v;
    if (t == 1023) g_bsum[blockIdx.x] = sh[1023];
}

__global__ void scan_tops_kernel(int nb) {
    __shared__ int sh[64];
    int t = threadIdx.x;
    int v = (t < nb) ? g_bsum[t] : 0;
    sh[t] = v;
    __syncthreads();
    #pragma unroll
    for (int o = 1; o < 64; o <<= 1) {
        int add = (t >= o) ? sh[t - o] : 0;
        __syncthreads();
        sh[t] += add;
        __syncthreads();
    }
    g_bsum[t] = sh[t] - v;
}

__global__ void scan_add_kernel(int Nn, int E) {
    int i = blockIdx.x * blockDim.x + threadIdx.x;
    if (i < Nn) {
        int o = g_off[i] + g_bsum[i >> 10];
        g_off[i] = o;
        g_cur[i] = o;
    }
    if (i == 0) g_off[Nn] = E;
}

__global__ void scatter_kernel(const int* __restrict__ src0,
                               const int* __restrict__ dst0,
                               const int* __restrict__ etype, int E) {
    int e = blockIdx.x * blockDim.x + threadIdx.x;
    if (e >= E) return;
    int d = dst0[e];
    int pos = atomicAdd(&g_cur[d], 1);
    g_csr_pack[pos] = src0[e] | (etype[e] << 20);
}

// ---------------- TF32 tensor-core GEMM, cp.async double-buffered ----------------
__device__ __forceinline__ uint32_t f2tf32(float x) {
    uint32_t r;
    asm("cvt.rna.tf32.f32 %0, %1;" : "=r"(r) : "f"(x));
    return r;
}

__device__ __forceinline__ void mma_tf32(float* c, const uint32_t* a, const uint32_t* b) {
    asm volatile(
        "mma.sync.aligned.m16n8k8.row.col.f32.tf32.tf32.f32 "
        "{%0,%1,%2,%3}, {%4,%5,%6,%7}, {%8,%9}, {%0,%1,%2,%3};"
        : "+f"(c[0]), "+f"(c[1]), "+f"(c[2]), "+f"(c[3])
        : "r"(a[0]), "r"(a[1]), "r"(a[2]), "r"(a[3]), "r"(b[0]), "r"(b[1]));
}

__device__ __forceinline__ uint32_t smem_u32(const void* p) {
    return (uint32_t)__cvta_generic_to_shared(p);
}

#define AS_LD 36
#define BS_LD 132
#define GEMM_SMEM_BYTES ((2 * 128 * AS_LD + 2 * 32 * BS_LD) * 4)

__global__ void __launch_bounds__(256, 2)
gemm_tf32_kernel(const float* __restrict__ A, const float* __restrict__ B,
                 float* __restrict__ C, int M, int N, int K) {
    extern __shared__ float dynsmem[];
    float* AsBase = dynsmem;
    float* BsBase = dynsmem + 2 * 128 * AS_LD;

    const int tid = threadIdx.x;
    const int lane = tid & 31, wid = tid >> 5;
    const int wm = (wid >> 2) * 64;
    const int wn = (wid & 3) * 32;
    const int bm0 = blockIdx.x * 128;
    const int bn0 = blockIdx.y * 128;

    const int a_r = tid >> 3;
    const int a_c = (tid & 7) * 4;
    const int b_r = tid >> 5;
    const int b_c = (tid & 31) * 4;

    float acc[4][4][4];
    #pragma unroll
    for (int i = 0; i < 4; ++i)
        #pragma unroll
        for (int j = 0; j < 4; ++j)
            #pragma unroll
            for (int k = 0; k < 4; ++k) acc[i][j][k] = 0.f;

    const int nk = K >> 5;

    auto load_stage = [&](int kt, int buf) {
        const int k0 = kt * 32;
        float* As = AsBase + buf * 128 * AS_LD;
        float* Bs = BsBase + buf * 32 * BS_LD;
        #pragma unroll
        for (int i = 0; i < 4; ++i) {
            int row = a_r + 32 * i;
            int grow = bm0 + row;
            int ok = (grow < M);
            const float* src = A + (size_t)(ok ? grow : 0) * K + k0 + a_c;
            uint32_t dst = smem_u32(&As[row * AS_LD + a_c]);
            int nb = ok ? 16 : 0;
            asm volatile("cp.async.ca.shared.global [%0], [%1], 16, %2;"
                         :: "r"(dst), "l"(src), "r"(nb));
        }
        #pragma unroll
        for (int i = 0; i < 4; ++i) {
            int row = b_r + 8 * i;
            const float* src = B + (size_t)(k0 + row) * N + bn0 + b_c;
            uint32_t dst = smem_u32(&Bs[row * BS_LD + b_c]);
            asm volatile("cp.async.ca.shared.global [%0], [%1], 16;"
                         :: "r"(dst), "l"(src));
        }
        asm volatile("cp.async.commit_group;");
    };

    load_stage(0, 0);

    for (int kt = 0; kt < nk; ++kt) {
        const int buf = kt & 1;
        if (kt + 1 < nk) load_stage(kt + 1, buf ^ 1);
        else asm volatile("cp.async.commit_group;");
        asm volatile("cp.async.wait_group 1;");
        __syncthreads();

        const float* as = AsBase + buf * 128 * AS_LD;
        const float* bs = BsBase + buf * 32 * BS_LD;
        #pragma unroll
        for (int kk = 0; kk < 4; ++kk) {
            const int kb = kk * 8;
            uint32_t afrag[4][4], bfrag[4][2];
            #pragma unroll
            for (int mt = 0; mt < 4; ++mt) {
                int r0 = wm + mt * 16 + (lane >> 2);
                int c0 = kb + (lane & 3);
                afrag[mt][0] = f2tf32(as[r0 * AS_LD + c0]);
                afrag[mt][1] = f2tf32(as[(r0 + 8) * AS_LD + c0]);
                afrag[mt][2] = f2tf32(as[r0 * AS_LD + c0 + 4]);
                afrag[mt][3] = f2tf32(as[(r0 + 8) * AS_LD + c0 + 4]);
            }
            #pragma unroll
            for (int nt = 0; nt < 4; ++nt) {
                int n0 = wn + nt * 8 + (lane >> 2);
                int kr = kb + (lane & 3);
                bfrag[nt][0] = f2tf32(bs[kr * BS_LD + n0]);
                bfrag[nt][1] = f2tf32(bs[(kr + 4) * BS_LD + n0]);
            }
            #pragma unroll
            for (int mt = 0; mt < 4; ++mt)
                #pragma unroll
                for (int nt = 0; nt < 4; ++nt)
                    mma_tf32(acc[mt][nt], afrag[mt], bfrag[nt]);
        }
        __syncthreads();
    }

    #pragma unroll
    for (int mt = 0; mt < 4; ++mt) {
        int row0 = bm0 + wm + mt * 16 + (lane >> 2);
        #pragma unroll
        for (int nt = 0; nt < 4; ++nt) {
            int col0 = bn0 + wn + nt * 8 + (lane & 3) * 2;
            if (row0 < M)
                *reinterpret_cast<float2*>(C + (size_t)row0 * N + col0) =
                    make_float2(acc[mt][nt][0], acc[mt][nt][1]);
            if (row0 + 8 < M)
                *reinterpret_cast<float2*>(C + (size_t)(row0 + 8) * N + col0) =
                    make_float2(acc[mt][nt][2], acc[mt][nt][3]);
        }
    }
}

// ---------------- node attention logits (layer 1) --------------------------------
__global__ void attn1_kernel(const float* __restrict__ as_,
                             const float* __restrict__ ad_, int Nn) {
    int idx = blockIdx.x * blockDim.x + threadIdx.x;
    if (idx >= Nn * 8) return;
    int n = idx >> 3, h = idx & 7;
    const float* hp = g_h1 + (size_t)n * 256 + h * 32;
    const float* asp = as_ + h * 32;
    const float* adp = ad_ + h * 32;
    float s = 0.f, d = 0.f;
    #pragma unroll
    for (int c = 0; c < 32; ++c) {
        float v = hp[c];
        s += v * asp[c];
        d += v * adp[c];
    }
    g_als1[idx] = s;
    g_ald1[idx] = d;
}

// ---------------- layer-1: warp-per-node softmax+aggregate+bias+LN+ELU -----------
// channel ch = lane*8+k; head = lane>>2 (all 8 channels of a lane share one head).
// Each lane accumulates den/sumrae for its own head over ALL edges -> no reductions.
__global__ void __launch_bounds__(256)
gat1_warp_kernel(const float* __restrict__ b, const float* __restrict__ g,
                 const float* __restrict__ beta, int Nn) {
    __shared__ float sh_rae[48];
    const int t = threadIdx.x;
    if (t < 48) sh_rae[t] = g_rae[t];
    __syncthreads();

    const int d = blockIdx.x * 8 + (t >> 5);
    if (d >= Nn) return;
    const int lane = t & 31;
    const int hl = lane >> 2;

    const int beg = g_off[d], end = g_off[d + 1];
    const float aldl = g_ald1[d * 8 + hl];

    float acc[8] = {0.f, 0.f, 0.f, 0.f, 0.f, 0.f, 0.f, 0.f};
    float den = 0.f, sumrae = 0.f;

    #pragma unroll 2
    for (int e = beg; e < end; ++e) {
        int p = g_csr_pack[e];
        int s = p & 0xFFFFF, r = p >> 20;
        float rv = sh_rae[r * 8 + hl];
        float a = g_als1[s * 8 + hl] + aldl + rv;
        a = a > 0.f ? a : 0.2f * a;
        float ex = __expf(a);
        den += ex;
        sumrae += rv;
        const float4* hp = reinterpret_cast<const float4*>(g_h1 + (size_t)s * 256);
        float4 v0 = hp[lane * 2], v1 = hp[lane * 2 + 1];
        acc[0] += ex * v0.x; acc[1] += ex * v0.y;
        acc[2] += ex * v0.z; acc[3] += ex * v0.w;
        acc[4] += ex * v1.x; acc[5] += ex * v1.y;
        acc[6] += ex * v1.z; acc[7] += ex * v1.w;
    }

    // self loop
    float deg = (float)(end - beg);
    float asf = g_als1[d * 8 + hl] + aldl + sumrae / fmaxf(deg, 1.f);
    asf = asf > 0.f ? asf : 0.2f * asf;
    float exs = __expf(asf);
    den += exs;
    {
        const float4* hp = reinterpret_cast<const float4*>(g_h1 + (size_t)d * 256);
        float4 v0 = hp[lane * 2], v1 = hp[lane * 2 + 1];
        acc[0] += exs * v0.x; acc[1] += exs * v0.y;
        acc[2] += exs * v0.z; acc[3] += exs * v0.w;
        acc[4] += exs * v1.x; acc[5] += exs * v1.y;
        acc[6] += exs * v1.z; acc[7] += exs * v1.w;
    }

    // weights + bias
    float inv = 1.f / (den + 1e-16f);
    const float4* bp = reinterpret_cast<const float4*>(b);
    float4 b0 = bp[lane * 2], b1 = bp[lane * 2 + 1];
    float v[8];
    v[0] = acc[0] * inv + b0.x; v[1] = acc[1] * inv + b0.y;
    v[2] = acc[2] * inv + b0.z; v[3] = acc[3] * inv + b0.w;
    v[4] = acc[4] * inv + b1.x; v[5] = acc[5] * inv + b1.y;
    v[6] = acc[6] * inv + b1.z; v[7] = acc[7] * inv + b1.w;

    // LayerNorm across 256 channels (warp shuffle reduction)
    float s1 = 0.f, s2 = 0.f;
    #pragma unroll
    for (int k = 0; k < 8; ++k) { s1 += v[k]; s2 += v[k] * v[k]; }
    #pragma unroll
    for (int o = 16; o; o >>= 1) {
        s1 += __shfl_xor_sync(0xffffffffu, s1, o);
        s2 += __shfl_xor_sync(0xffffffffu, s2, o);
    }
    float m = s1 * (1.f / 256.f);
    float var = s2 * (1.f / 256.f) - m * m;
    float rstd = rsqrtf(var + 1e-5f);

    const float4* gp = reinterpret_cast<const float4*>(g);
    const float4* betap = reinterpret_cast<const float4*>(beta);
    float4 g0 = gp[lane * 2], g1v = gp[lane * 2 + 1];
    float4 be0 = betap[lane * 2], be1 = betap[lane * 2 + 1];
    float gg[8] = {g0.x, g0.y, g0.z, g0.w, g1v.x, g1v.y, g1v.z, g1v.w};
    float bb[8] = {be0.x, be0.y, be0.z, be0.w, be1.x, be1.y, be1.z, be1.w};
    float y[8];
    #pragma unroll
    for (int k = 0; k < 8; ++k) {
        float yy = (v[k] - m) * rstd * gg[k] + bb[k];
        y[k] = yy > 0.f ? yy : expm1f(yy);
    }
    float4* op = reinterpret_cast<float4*>(g_out1 + (size_t)d * 256);
    op[lane * 2]     = make_float4(y[0], y[1], y[2], y[3]);
    op[lane * 2 + 1] = make_float4(y[4], y[5], y[6], y[7]);
}

// ---------------- layer-2 attention logits ----------------------------------------
__global__ void attn2_kernel(const float* __restrict__ as_,
                             const float* __restrict__ ad_) {
    int n = blockIdx.x, t = threadIdx.x;  // 128
    float v = g_h2[(size_t)n * 128 + t];
    __shared__ float s1[128], s2[128];
    s1[t] = v * as_[t]; s2[t] = v * ad_[t];
    __syncthreads();
    #pragma unroll
    for (int off = 64; off > 0; off >>= 1) {
        if (t < off) { s1[t] += s1[t + off]; s2[t] += s2[t + off]; }
        __syncthreads();
    }
    if (t == 0) { g_als2[n] = s1[0]; g_ald2[n] = s2[0]; }
}

// ---------------- layer-2: warp-per-node softmax+aggregate+bias+LN ---------------
__global__ void __launch_bounds__(256)
gat2_warp_kernel(const float* __restrict__ b, const float* __restrict__ g,
                 const float* __restrict__ beta, float* __restrict__ out, int Nn) {
    const int t = threadIdx.x;
    const int d = blockIdx.x * 8 + (t >> 5);
    if (d >= Nn) return;
    const int lane = t & 31;

    const int beg = g_off[d], end = g_off[d + 1];
    const float ald = g_ald2[d];

    float acc[4] = {0.f, 0.f, 0.f, 0.f};
    float den = 0.f;

    #pragma unroll 2
    for (int e = beg; e < end; ++e) {
        int s = g_csr_pack[e] & 0xFFFFF;
        float a = g_als2[s] + ald;
        a = a > 0.f ? a : 0.2f * a;
        float ex = __expf(a);
        den += ex;
        float4 v = reinterpret_cast<const float4*>(g_h2 + (size_t)s * 128)[lane];
        acc[0] += ex * v.x; acc[1] += ex * v.y;
        acc[2] += ex * v.z; acc[3] += ex * v.w;
    }

    float asf = g_als2[d] + ald;
    asf = asf > 0.f ? asf : 0.2f * asf;
    float exs = __expf(asf);
    den += exs;
    {
        float4 v = reinterpret_cast<const float4*>(g_h2 + (size_t)d * 128)[lane];
        acc[0] += exs * v.x; acc[1] += exs * v.y;
        acc[2] += exs * v.z; acc[3] += exs * v.w;
    }

    float inv = 1.f / (den + 1e-16f);
    float4 bv = reinterpret_cast<const float4*>(b)[lane];
    float v[4];
    v[0] = acc[0] * inv + bv.x; v[1] = acc[1] * inv + bv.y;
    v[2] = acc[2] * inv + bv.z; v[3] = acc[3] * inv + bv.w;

    float s1 = 0.f, s2 = 0.f;
    #pragma unroll
    for (int k = 0; k < 4; ++k) { s1 += v[k]; s2 += v[k] * v[k]; }
    #pragma unroll
    for (int o = 16; o; o >>= 1) {
        s1 += __shfl_xor_sync(0xffffffffu, s1, o);
        s2 += __shfl_xor_sync(0xffffffffu, s2, o);
    }
    float m = s1 * (1.f / 128.f);
    float var = s2 * (1.f / 128.f) - m * m;
    float rstd = rsqrtf(var + 1e-5f);

    float4 gv = reinterpret_cast<const float4*>(g)[lane];
    float4 bev = reinterpret_cast<const float4*>(beta)[lane];
    float4 o4;
    o4.x = (v[0] - m) * rstd * gv.x + bev.x;
    o4.y = (v[1] - m) * rstd * gv.y + bev.y;
    o4.z = (v[2] - m) * rstd * gv.z + bev.z;
    o4.w = (v[3] - m) * rstd * gv.w + bev.w;
    reinterpret_cast<float4*>(out + (size_t)d * 128)[lane] = o4;
}

// ---------------- launch -----------------------------------------------------------
extern "C" void kernel_launch(void* const* d_in, const int* in_sizes, int n_in,
                              void* d_out, int out_size) {
    const float* x       = (const float*)d_in[0];
    const int*   ei      = (const int*)d_in[1];
    const int*   etype   = (const int*)d_in[2];
    const float* rel_emb = (const float*)d_in[3];
    const float* W1      = (const float*)d_in[4];
    const float* as1     = (const float*)d_in[5];
    const float* ad1     = (const float*)d_in[6];
    const float* We1     = (const float*)d_in[7];
    const float* ae1     = (const float*)d_in[8];
    const float* b1      = (const float*)d_in[9];
    const float* g1      = (const float*)d_in[10];
    const float* beta1   = (const float*)d_in[11];
    const float* W2      = (const float*)d_in[12];
    const float* as2     = (const float*)d_in[13];
    const float* ad2     = (const float*)d_in[14];
    const float* b2      = (const float*)d_in[15];
    const float* g2      = (const float*)d_in[16];
    const float* beta2   = (const float*)d_in[17];
    float* out = (float*)d_out;

    const int E = in_sizes[2];
    const int Nn = in_sizes[0] / 768;
    const int* src0 = ei;
    const int* dst0 = ei + E;
    const int nb = (Nn + 1023) / 1024;

    float *ph1, *pout1, *ph2;
    cudaGetSymbolAddress((void**)&ph1, g_h1);
    cudaGetSymbolAddress((void**)&pout1, g_out1);
    cudaGetSymbolAddress((void**)&ph2, g_h2);

    static int smem_configured = 0;
    if (!smem_configured) {
        cudaFuncSetAttribute(gemm_tf32_kernel,
                             cudaFuncAttributeMaxDynamicSharedMemorySize,
                             GEMM_SMEM_BYTES);
        smem_configured = 1;
    }

    // CSR build + collapsed edge attention
    init_kernel<<<(Nn + 255) / 256, 256>>>(Nn);
    prep_kernel<<<1, 512>>>(We1, ae1, rel_emb);
    hist_kernel<<<(E + 255) / 256, 256>>>(dst0, E);
    scan_part_kernel<<<nb, 1024>>>(Nn);
    scan_tops_kernel<<<1, 64>>>(nb);
    scan_add_kernel<<<(Nn + 255) / 256, 256>>>(Nn, E);
    scatter_kernel<<<(E + 255) / 256, 256>>>(src0, dst0, etype, E);

    // GEMM1: h1 = x @ W1   [Nn,768] x [768,256]
    {
        dim3 grid((Nn + 127) / 128, 2);
        gemm_tf32_kernel<<<grid, 256, GEMM_SMEM_BYTES>>>(x, W1, ph1, Nn, 256, 768);
    }
    attn1_kernel<<<(Nn * 8 + 255) / 256, 256>>>(as1, ad1, Nn);
    gat1_warp_kernel<<<(Nn + 7) / 8, 256>>>(b1, g1, beta1, Nn);

    // GEMM2: h2 = out1 @ W2   [Nn,256] x [256,128]
    {
        dim3 grid((Nn + 127) / 128, 1);
        gemm_tf32_kernel<<<grid, 256, GEMM_SMEM_BYTES>>>(pout1, W2, ph2, Nn, 128, 256);
    }
    attn2_kernel<<<Nn, 128>>>(as2, ad2);
    gat2_warp_kernel<<<(Nn + 7) / 8, 256>>>(b2, g2, beta2, out, Nn);
}